// round 2
// baseline (speedup 1.0000x reference)
#include <cuda_runtime.h>
#include <math.h>
#include <stdint.h>

// ---------------- problem constants ----------------
#define Bb 2
#define Ss 2048
#define Dd 512
#define NLAYERS 6
#define DI 1024
#define Hh 8
#define Nn 16
#define Kk 4
#define Vv 32000
#define TOT (2*DI + Hh + 2*Hh*Nn)   // 2312
#define ROWS (Bb*Ss)                // 4096

// ---------------- scratch (static device globals; no allocation) ----------------
__device__ float g_x [ROWS*Dd];        // residual stream
__device__ float g_xn[ROWS*Dd];        // normed x / final LN out
__device__ float g_p [ROWS*TOT];       // in_proj output
__device__ float g_xc[ROWS*DI];        // conv+silu
__device__ float g_dt[ROWS*Hh];        // softplus(dt)
__device__ float g_xin[ROWS*Hh];       // head means
__device__ float g_hs[ROWS*Hh*Nn];     // scan states
__device__ float g_y [ROWS*Hh];        // y after C-contraction
__device__ float g_yi[ROWS*DI];        // y_proj * silu(z)

// ---------------- helpers ----------------
__device__ __forceinline__ float blockReduceSum256(float v, float* sh) {
    int t = threadIdx.x;
    sh[t] = v; __syncthreads();
    #pragma unroll
    for (int o = 128; o > 0; o >>= 1) {
        if (t < o) sh[t] += sh[t + o];
        __syncthreads();
    }
    float r = sh[0];
    __syncthreads();
    return r;
}

__device__ __forceinline__ float siluf(float v) { return v / (1.f + expf(-v)); }
__device__ __forceinline__ float softplusf(float v) {
    // stable logaddexp(v, 0)
    return (v > 0.f) ? (v + log1pf(expf(-v))) : log1pf(expf(v));
}

// ---------------- embedding gather ----------------
__global__ void k_embed(const int* __restrict__ tok, const float* __restrict__ emb) {
    int i = blockIdx.x * blockDim.x + threadIdx.x;
    if (i < ROWS * Dd) {
        int r = i / Dd, d = i - r * Dd;
        g_x[i] = emb[(size_t)tok[r] * Dd + d];
    }
}

// ---------------- rmsnorm ----------------
__global__ void k_rms(const float* __restrict__ rms_w) {
    __shared__ float sh[256];
    int r = blockIdx.x, t = threadIdx.x;
    float v0 = g_x[(size_t)r*Dd + t];
    float v1 = g_x[(size_t)r*Dd + t + 256];
    float ss = blockReduceSum256(v0*v0 + v1*v1, sh);
    float sc = rsqrtf(ss / (float)Dd + 1e-6f);
    g_xn[(size_t)r*Dd + t]       = v0 * sc * rms_w[t];
    g_xn[(size_t)r*Dd + t + 256] = v1 * sc * rms_w[t + 256];
}

// ---------------- generic SGEMM: C[M,N] = A[M,K] * B[N,K]^T (+res)(+bias) ----------------
template<bool ADD_RES, bool ADD_BIAS>
__global__ __launch_bounds__(256)
void k_gemm(const float* __restrict__ A, const float* __restrict__ B,
            const float* __restrict__ Res, const float* __restrict__ bias,
            float* __restrict__ C, int M, int N, int Kd)
{
    const int BM = 128, BN = 64, BK = 16, TM = 8, TN = 4;
    __shared__ float As[BK][BM + 1];
    __shared__ float Bs[BK][BN + 4];

    int tid  = threadIdx.x;             // 256 threads
    int bm   = blockIdx.y * BM;
    int bn   = blockIdx.x * BN;
    int tcol = tid & 15;
    int trow = tid >> 4;
    int m0   = trow * TM;
    int n0   = tcol * TN;

    float acc[TM][TN];
    #pragma unroll
    for (int i = 0; i < TM; i++)
        #pragma unroll
        for (int j = 0; j < TN; j++) acc[i][j] = 0.f;

    for (int k0 = 0; k0 < Kd; k0 += BK) {
        // A tile: 128x16 = 512 float4, 2 per thread
        #pragma unroll
        for (int l = 0; l < 2; l++) {
            int id = tid + l * 256;
            int ar = id >> 2;
            int ac = (id & 3) * 4;
            float4 v = *(const float4*)(A + (size_t)(bm + ar) * Kd + k0 + ac);
            As[ac+0][ar] = v.x; As[ac+1][ar] = v.y;
            As[ac+2][ar] = v.z; As[ac+3][ar] = v.w;
        }
        // B tile: 64x16 = 256 float4, 1 per thread (guard N)
        {
            int br = tid >> 2;
            int bc = (tid & 3) * 4;
            float4 v = make_float4(0.f, 0.f, 0.f, 0.f);
            if (bn + br < N)
                v = *(const float4*)(B + (size_t)(bn + br) * Kd + k0 + bc);
            Bs[bc+0][br] = v.x; Bs[bc+1][br] = v.y;
            Bs[bc+2][br] = v.z; Bs[bc+3][br] = v.w;
        }
        __syncthreads();
        #pragma unroll
        for (int k = 0; k < BK; k++) {
            float a[TM], b[TN];
            #pragma unroll
            for (int i = 0; i < TM; i++) a[i] = As[k][m0 + i];
            #pragma unroll
            for (int j = 0; j < TN; j++) b[j] = Bs[k][n0 + j];
            #pragma unroll
            for (int i = 0; i < TM; i++)
                #pragma unroll
                for (int j = 0; j < TN; j++) acc[i][j] += a[i] * b[j];
        }
        __syncthreads();
    }

    #pragma unroll
    for (int i = 0; i < TM; i++) {
        int m = bm + m0 + i;
        #pragma unroll
        for (int j = 0; j < TN; j++) {
            int n = bn + n0 + j;
            if (n < N) {
                float v = acc[i][j];
                if (ADD_BIAS) v += bias[n];
                if (ADD_RES)  v += Res[(size_t)m * N + n];
                C[(size_t)m * N + n] = v;
            }
        }
    }
}

// ---------------- causal depthwise conv (K=4) + SiLU ----------------
__global__ void k_conv(const float* __restrict__ cw) {
    int i = blockIdx.x * blockDim.x + threadIdx.x;
    if (i >= ROWS * DI) return;
    int c = i % DI;
    int r = i / DI;
    int s = r % Ss;
    int b = r / Ss;
    float acc = 0.f;
    #pragma unroll
    for (int k = 0; k < Kk; k++) {
        int sp = s + k - (Kk - 1);
        if (sp >= 0)
            acc += g_p[(size_t)(b*Ss + sp) * TOT + DI + c] * cw[c*Kk + k];
    }
    g_xc[i] = siluf(acc);
}

// ---------------- dt softplus + per-head mean of conv output ----------------
__global__ void k_dtx(const float* __restrict__ dtb) {
    int r = blockIdx.x;
    int w = threadIdx.x >> 5;       // head 0..7
    int lane = threadIdx.x & 31;
    float s = 0.f;
    #pragma unroll
    for (int j = 0; j < 4; j++)
        s += g_xc[(size_t)r*DI + w*128 + lane + 32*j];
    #pragma unroll
    for (int o = 16; o > 0; o >>= 1) s += __shfl_xor_sync(0xffffffffu, s, o);
    if (lane == 0) {
        g_xin[r*Hh + w] = s * (1.f / 128.f);
        float dt = g_p[(size_t)r*TOT + 2*DI + w] + dtb[w];
        g_dt[r*Hh + w] = softplusf(dt);
    }
}

// ---------------- parallel associative scan: one block per (b,h,n) chain ----------------
__global__ __launch_bounds__(256)
void k_scan(const float* __restrict__ A_log) {
    const int CH = Ss / 256;   // 8
    int chain = blockIdx.x;
    int n = chain % Nn;
    int h = (chain / Nn) % Hh;
    int b = chain / (Nn * Hh);
    float Ah = -expf(A_log[h]);

    int t = threadIdx.x;
    float hloc[CH], cA[CH];
    float a = 1.f, hv = 0.f;
    int s0 = t * CH;
    #pragma unroll
    for (int j = 0; j < CH; j++) {
        int r = b*Ss + s0 + j;
        float dt = g_dt[r*Hh + h];
        float dA = expf(dt * Ah);
        float u  = dt * g_xin[r*Hh + h] * g_p[(size_t)r*TOT + 2*DI + Hh + h*Nn + n];
        hv = dA * hv + u;
        a *= dA;
        hloc[j] = hv; cA[j] = a;
    }
    __shared__ float sA[256], sB[256];
    sA[t] = a; sB[t] = hv;
    __syncthreads();
    // inclusive Hillis-Steele scan of affine transforms (A,B): compose
    for (int off = 1; off < 256; off <<= 1) {
        float pa = 0.f, pb = 0.f;
        if (t >= off) { pa = sA[t - off]; pb = sB[t - off]; }
        __syncthreads();
        if (t >= off) { sB[t] = sA[t] * pb + sB[t]; sA[t] = sA[t] * pa; }
        __syncthreads();
    }
    float hin = (t == 0) ? 0.f : sB[t - 1];
    #pragma unroll
    for (int j = 0; j < CH; j++) {
        int r = b*Ss + s0 + j;
        g_hs[((size_t)r*Hh + h) * Nn + n] = hloc[j] + cA[j] * hin;
    }
}

// ---------------- y = sum_n h*C ----------------
__global__ void k_yred() {
    int i = blockIdx.x * blockDim.x + threadIdx.x;
    if (i >= ROWS * Hh) return;
    int h = i % Hh;
    int r = i / Hh;
    const float* hs = &g_hs[(size_t)i * Nn];
    const float* Cp = &g_p[(size_t)r*TOT + 2*DI + Hh + Hh*Nn + h*Nn];
    float s = 0.f;
    #pragma unroll
    for (int n = 0; n < Nn; n++) s += hs[n] * Cp[n];
    g_y[i] = s;
}

// ---------------- y_proj + gate: yi = (y @ yw^T) * silu(z) ----------------
__global__ void k_ymix(const float* __restrict__ yw) {
    int i = blockIdx.x * blockDim.x + threadIdx.x;
    if (i >= ROWS * DI) return;
    int c = i % DI;
    int r = i / DI;
    float s = 0.f;
    #pragma unroll
    for (int h = 0; h < Hh; h++) s += g_y[r*Hh + h] * yw[c*Hh + h];
    float z = g_p[(size_t)r*TOT + c];
    g_yi[i] = s * siluf(z);
}

// ---------------- final layernorm ----------------
__global__ void k_ln(const float* __restrict__ ln_w, const float* __restrict__ ln_b) {
    __shared__ float sh[256];
    int r = blockIdx.x, t = threadIdx.x;
    float v0 = g_x[(size_t)r*Dd + t];
    float v1 = g_x[(size_t)r*Dd + t + 256];
    float mu = blockReduceSum256(v0 + v1, sh) / (float)Dd;
    float d0 = v0 - mu, d1 = v1 - mu;
    float var = blockReduceSum256(d0*d0 + d1*d1, sh) / (float)Dd;
    float sc = rsqrtf(var + 1e-5f);
    g_xn[(size_t)r*Dd + t]       = d0 * sc * ln_w[t]       + ln_b[t];
    g_xn[(size_t)r*Dd + t + 256] = d1 * sc * ln_w[t + 256] + ln_b[t + 256];
}

// ---------------- launch ----------------
extern "C" void kernel_launch(void* const* d_in, const int* in_sizes, int n_in,
                              void* d_out, int out_size) {
    const int*   tok    = (const int*)  d_in[0];
    const float* emb    = (const float*)d_in[1];
    const float* rms_w  = (const float*)d_in[2];
    const float* in_w   = (const float*)d_in[3];
    const float* conv_w = (const float*)d_in[4];
    const float* dt_b   = (const float*)d_in[5];
    const float* A_log  = (const float*)d_in[6];
    const float* y_w    = (const float*)d_in[7];
    const float* out_w  = (const float*)d_in[8];
    const float* ln_w   = (const float*)d_in[9];
    const float* ln_b   = (const float*)d_in[10];
    const float* head_w = (const float*)d_in[11];
    const float* head_b = (const float*)d_in[12];
    float* out = (float*)d_out;

    float *p_x, *p_xn, *p_yi;
    cudaGetSymbolAddress((void**)&p_x,  g_x);
    cudaGetSymbolAddress((void**)&p_xn, g_xn);
    cudaGetSymbolAddress((void**)&p_yi, g_yi);
    float* p_p;
    cudaGetSymbolAddress((void**)&p_p, g_p);

    k_embed<<<(ROWS*Dd + 255)/256, 256>>>(tok, emb);

    for (int L = 0; L < NLAYERS; L++) {
        k_rms<<<ROWS, 256>>>(rms_w + (size_t)L*Dd);

        // p = xn @ in_w[L]^T   (M=4096, N=2312, K=512)
        dim3 g1((TOT + 63)/64, ROWS/128);
        k_gemm<false,false><<<g1, 256>>>(p_xn, in_w + (size_t)L*TOT*Dd,
                                         nullptr, nullptr, p_p, ROWS, TOT, Dd);

        k_conv<<<(ROWS*DI + 255)/256, 256>>>(conv_w + (size_t)L*DI*Kk);
        k_dtx <<<ROWS, 256>>>(dt_b + (size_t)L*Hh);
        k_scan<<<Bb*Hh*Nn, 256>>>(A_log + (size_t)L*Hh);
        k_yred<<<(ROWS*Hh + 255)/256, 256>>>();
        k_ymix<<<(ROWS*DI + 255)/256, 256>>>(y_w + (size_t)L*DI*Hh);

        // x = yi @ out_w[L]^T + x   (M=4096, N=512, K=1024), in-place residual
        dim3 g2((Dd + 63)/64, ROWS/128);
        k_gemm<true,false><<<g2, 256>>>(p_yi, out_w + (size_t)L*Dd*DI,
                                        p_x, nullptr, p_x, ROWS, Dd, DI);
    }

    k_ln<<<ROWS, 256>>>(ln_w, ln_b);

    // out = xn @ head_w^T + head_b   (M=4096, N=32000, K=512)
    dim3 g3((Vv + 63)/64, ROWS/128);
    k_gemm<false,true><<<g3, 256>>>(p_xn, head_w, nullptr, head_b,
                                    out, ROWS, Vv, Dd);
}

// round 6
// speedup vs baseline: 2.2433x; 2.2433x over previous
#include <cuda_runtime.h>
#include <cuda_bf16.h>
#include <math.h>
#include <stdint.h>

// ---------------- problem constants ----------------
#define Bb 2
#define Ss 2048
#define Dd 512
#define NLAYERS 6
#define DI 1024
#define Hh 8
#define Nn 16
#define Kk 4
#define Vv 32000
#define TOT (2*DI + Hh + 2*Hh*Nn)   // 2312
#define ROWS (Bb*Ss)                // 4096

// ---------------- scratch (static device globals; no allocation) ----------------
__device__ float g_x [ROWS*Dd];
__device__ float g_xn[ROWS*Dd];
__device__ float g_p [ROWS*TOT];
__device__ float g_xc[ROWS*DI];
__device__ float g_dt[ROWS*Hh];
__device__ float g_xin[ROWS*Hh];
__device__ float g_hs[ROWS*Hh*Nn];
__device__ float g_y [ROWS*Hh];
__device__ float g_yi[ROWS*DI];
// bf16 split buffers
__device__ __align__(128) __nv_bfloat16 g_ahi[ROWS*DI];
__device__ __align__(128) __nv_bfloat16 g_alo[ROWS*DI];
__device__ __align__(128) __nv_bfloat16 g_whi[(size_t)Vv*Dd];
__device__ __align__(128) __nv_bfloat16 g_wlo[(size_t)Vv*Dd];

// ---------------- small helpers ----------------
__device__ __forceinline__ float blockReduceSum256(float v, float* sh) {
    int t = threadIdx.x;
    sh[t] = v; __syncthreads();
    #pragma unroll
    for (int o = 128; o > 0; o >>= 1) {
        if (t < o) sh[t] += sh[t + o];
        __syncthreads();
    }
    float r = sh[0];
    __syncthreads();
    return r;
}
__device__ __forceinline__ float siluf(float v) { return v / (1.f + expf(-v)); }
__device__ __forceinline__ float softplusf(float v) {
    return (v > 0.f) ? (v + log1pf(expf(-v))) : log1pf(expf(v));
}

// ---------------- MMA primitives (arch-neutral, sm_80+) ----------------
__device__ __forceinline__ void cp16(uint32_t s, const void* g, uint32_t sz) {
    asm volatile("cp.async.cg.shared.global [%0], [%1], 16, %2;"
                 :: "r"(s), "l"(g), "r"(sz) : "memory");
}
__device__ __forceinline__ void cp_commit() {
    asm volatile("cp.async.commit_group;" ::: "memory");
}
__device__ __forceinline__ void cp_wait1() {
    asm volatile("cp.async.wait_group 1;" ::: "memory");
}
__device__ __forceinline__ void cp_wait0() {
    asm volatile("cp.async.wait_group 0;" ::: "memory");
}
__device__ __forceinline__ void ldm4(uint32_t* r, uint32_t a) {
    asm volatile("ldmatrix.sync.aligned.m8n8.x4.shared.b16 {%0,%1,%2,%3}, [%4];"
                 : "=r"(r[0]), "=r"(r[1]), "=r"(r[2]), "=r"(r[3]) : "r"(a));
}
__device__ __forceinline__ void mma16816(float* d, const uint32_t* a,
                                         uint32_t b0, uint32_t b1) {
    asm volatile("mma.sync.aligned.m16n8k16.row.col.f32.bf16.bf16.f32 "
                 "{%0,%1,%2,%3}, {%4,%5,%6,%7}, {%8,%9}, {%0,%1,%2,%3};"
                 : "+f"(d[0]), "+f"(d[1]), "+f"(d[2]), "+f"(d[3])
                 : "r"(a[0]), "r"(a[1]), "r"(a[2]), "r"(a[3]), "r"(b0), "r"(b1));
}

// ---------------- fp32 -> bf16 hi/lo split ----------------
__global__ void k_cvt(const float* __restrict__ src, __nv_bfloat16* __restrict__ hi,
                      __nv_bfloat16* __restrict__ lo, int n) {
    int i = (blockIdx.x * blockDim.x + threadIdx.x) * 4;
    if (i >= n) return;
    float4 v = *(const float4*)(src + i);
    __nv_bfloat16 h0 = __float2bfloat16(v.x);
    __nv_bfloat16 h1 = __float2bfloat16(v.y);
    __nv_bfloat16 h2 = __float2bfloat16(v.z);
    __nv_bfloat16 h3 = __float2bfloat16(v.w);
    __nv_bfloat16 l0 = __float2bfloat16(v.x - __bfloat162float(h0));
    __nv_bfloat16 l1 = __float2bfloat16(v.y - __bfloat162float(h1));
    __nv_bfloat16 l2 = __float2bfloat16(v.z - __bfloat162float(h2));
    __nv_bfloat16 l3 = __float2bfloat16(v.w - __bfloat162float(h3));
    ((__nv_bfloat162*)(hi + i))[0] = __halves2bfloat162(h0, h1);
    ((__nv_bfloat162*)(hi + i))[1] = __halves2bfloat162(h2, h3);
    ((__nv_bfloat162*)(lo + i))[0] = __halves2bfloat162(l0, l1);
    ((__nv_bfloat162*)(lo + i))[1] = __halves2bfloat162(l2, l3);
}

// ---------------- HMMA GEMM: C[M,N] = A[M,K] @ B[N,K]^T (+res)(+bias) ----------------
// bf16 hi/lo split, 3 MMA passes, fp32 accum.
// CTA 128x128, BK=32, 256 threads (8 warps in 2x4), warp tile 64x32.
// Smem tiles: padded rows, 40 bf16 (80 B) stride. 4 tiles x 2 stages.
#define TILE_B   10240              // 128 rows * 80 B
#define STAGE_B  (4*TILE_B)         // Ahi, Alo, Bhi, Blo
#define GEMM_SMEM (2*STAGE_B)       // 81920

template<int ADD_RES, int ADD_BIAS>
__global__ void __launch_bounds__(256)
k_gemm_mma(const __nv_bfloat16* __restrict__ Ahi, const __nv_bfloat16* __restrict__ Alo,
           const __nv_bfloat16* __restrict__ Bhi, const __nv_bfloat16* __restrict__ Blo,
           const float* __restrict__ Res, const float* __restrict__ bias,
           float* __restrict__ C, int Nd, int Kd)
{
    extern __shared__ char smem[];
    const uint32_t sbase = (uint32_t)__cvta_generic_to_shared(smem);

    int tid = threadIdx.x, wid = tid >> 5, lane = tid & 31;
    int bm = blockIdx.y * 128, bn = blockIdx.x * 128;
    int wm = (wid >> 2) * 64, wn = (wid & 3) * 32;

    float acc[4][4][4];
    #pragma unroll
    for (int i = 0; i < 4; i++)
        #pragma unroll
        for (int j = 0; j < 4; j++)
            #pragma unroll
            for (int q = 0; q < 4; q++) acc[i][j][q] = 0.f;

    const int nch = Kd >> 5;

    // stage loader: 4 tiles, each 128 rows x 64 B (4x 16B chunks per row)
    auto load_stage = [&](int stage, int ch) {
        uint32_t sb = sbase + stage * STAGE_B;
        int k0 = ch << 5;
        #pragma unroll
        for (int j = 0; j < 2; j++) {
            int c = tid + j * 256;          // 0..511
            int row = c >> 2, q = c & 3;
            uint32_t so = (uint32_t)(row * 80 + q * 16);
            size_t ga = (size_t)(bm + row) * Kd + k0 + q * 8;
            cp16(sb + 0*TILE_B + so, Ahi + ga, 16);
            cp16(sb + 1*TILE_B + so, Alo + ga, 16);
            int brow = bn + row;
            uint32_t sz = (brow < Nd) ? 16u : 0u;
            int brc = brow < Nd ? brow : (Nd - 1);
            size_t gb = (size_t)brc * Kd + k0 + q * 8;
            cp16(sb + 2*TILE_B + so, Bhi + gb, sz);
            cp16(sb + 3*TILE_B + so, Blo + gb, sz);
        }
        cp_commit();
    };

    load_stage(0, 0);

    for (int ch = 0; ch < nch; ch++) {
        if (ch + 1 < nch) { load_stage((ch + 1) & 1, ch + 1); cp_wait1(); }
        else               cp_wait0();
        __syncthreads();

        uint32_t sb = sbase + (ch & 1) * STAGE_B;
        uint32_t sAh = sb, sAl = sb + TILE_B, sBh = sb + 2*TILE_B, sBl = sb + 3*TILE_B;

        #pragma unroll
        for (int ks = 0; ks < 2; ks++) {
            uint32_t aH[4][4], aL[4][4];
            int arow = (lane & 15);
            int acb  = ks * 32 + ((lane & 16) ? 16 : 0);
            #pragma unroll
            for (int mt = 0; mt < 4; mt++) {
                uint32_t ao = (uint32_t)((wm + mt*16 + arow) * 80 + acb);
                ldm4(aH[mt], sAh + ao);
                ldm4(aL[mt], sAl + ao);
            }
            int brow = ((lane & 16) ? 8 : 0) + (lane & 7);
            int bcb  = ks * 32 + ((lane & 8) ? 16 : 0);
            #pragma unroll
            for (int ntp = 0; ntp < 2; ntp++) {
                uint32_t bo = (uint32_t)((wn + ntp*16 + brow) * 80 + bcb);
                uint32_t bh[4], bl[4];
                ldm4(bh, sBh + bo);
                ldm4(bl, sBl + bo);
                #pragma unroll
                for (int mt = 0; mt < 4; mt++) {
                    int nt0 = ntp * 2;
                    mma16816(acc[mt][nt0],   aH[mt], bh[0], bh[1]);
                    mma16816(acc[mt][nt0],   aH[mt], bl[0], bl[1]);
                    mma16816(acc[mt][nt0],   aL[mt], bh[0], bh[1]);
                    mma16816(acc[mt][nt0+1], aH[mt], bh[2], bh[3]);
                    mma16816(acc[mt][nt0+1], aH[mt], bl[2], bl[3]);
                    mma16816(acc[mt][nt0+1], aL[mt], bh[2], bh[3]);
                }
            }
        }
        __syncthreads();
    }

    // epilogue
    #pragma unroll
    for (int mt = 0; mt < 4; mt++) {
        int r0 = bm + wm + mt*16 + (lane >> 2);
        #pragma unroll
        for (int nt = 0; nt < 4; nt++) {
            int n = bn + wn + nt*8 + (lane & 3) * 2;
            if (n < Nd) {
                float2 v0 = make_float2(acc[mt][nt][0], acc[mt][nt][1]);
                float2 v1 = make_float2(acc[mt][nt][2], acc[mt][nt][3]);
                if (ADD_BIAS) {
                    float2 bv = *(const float2*)(bias + n);
                    v0.x += bv.x; v0.y += bv.y; v1.x += bv.x; v1.y += bv.y;
                }
                if (ADD_RES) {
                    float2 r0v = *(const float2*)(Res + (size_t)r0 * Nd + n);
                    float2 r1v = *(const float2*)(Res + (size_t)(r0+8) * Nd + n);
                    v0.x += r0v.x; v0.y += r0v.y; v1.x += r1v.x; v1.y += r1v.y;
                }
                *(float2*)(C + (size_t)r0 * Nd + n)     = v0;
                *(float2*)(C + (size_t)(r0+8) * Nd + n) = v1;
            }
        }
    }
}

// ---------------- embedding gather ----------------
__global__ void k_embed(const int* __restrict__ tok, const float* __restrict__ emb) {
    int i = blockIdx.x * blockDim.x + threadIdx.x;
    if (i < ROWS * Dd) {
        int r = i / Dd, d = i - r * Dd;
        g_x[i] = emb[(size_t)tok[r] * Dd + d];
    }
}

// ---------------- rmsnorm ----------------
__global__ void k_rms(const float* __restrict__ rms_w) {
    __shared__ float sh[256];
    int r = blockIdx.x, t = threadIdx.x;
    float v0 = g_x[(size_t)r*Dd + t];
    float v1 = g_x[(size_t)r*Dd + t + 256];
    float ss = blockReduceSum256(v0*v0 + v1*v1, sh);
    float sc = rsqrtf(ss / (float)Dd + 1e-6f);
    g_xn[(size_t)r*Dd + t]       = v0 * sc * rms_w[t];
    g_xn[(size_t)r*Dd + t + 256] = v1 * sc * rms_w[t + 256];
}

// ---------------- causal depthwise conv (K=4) + SiLU ----------------
__global__ void k_conv(const float* __restrict__ cw) {
    int i = blockIdx.x * blockDim.x + threadIdx.x;
    if (i >= ROWS * DI) return;
    int c = i % DI;
    int r = i / DI;
    int s = r % Ss;
    int b = r / Ss;
    float acc = 0.f;
    #pragma unroll
    for (int k = 0; k < Kk; k++) {
        int sp = s + k - (Kk - 1);
        if (sp >= 0)
            acc += g_p[(size_t)(b*Ss + sp) * TOT + DI + c] * cw[c*Kk + k];
    }
    g_xc[i] = siluf(acc);
}

// ---------------- dt softplus + per-head mean of conv output ----------------
__global__ void k_dtx(const float* __restrict__ dtb) {
    int r = blockIdx.x;
    int w = threadIdx.x >> 5;
    int lane = threadIdx.x & 31;
    float s = 0.f;
    #pragma unroll
    for (int j = 0; j < 4; j++)
        s += g_xc[(size_t)r*DI + w*128 + lane + 32*j];
    #pragma unroll
    for (int o = 16; o > 0; o >>= 1) s += __shfl_xor_sync(0xffffffffu, s, o);
    if (lane == 0) {
        g_xin[r*Hh + w] = s * (1.f / 128.f);
        float dt = g_p[(size_t)r*TOT + 2*DI + w] + dtb[w];
        g_dt[r*Hh + w] = softplusf(dt);
    }
}

// ---------------- parallel associative scan ----------------
__global__ __launch_bounds__(256)
void k_scan(const float* __restrict__ A_log) {
    const int CH = Ss / 256;
    int chain = blockIdx.x;
    int n = chain % Nn;
    int h = (chain / Nn) % Hh;
    int b = chain / (Nn * Hh);
    float Ah = -expf(A_log[h]);

    int t = threadIdx.x;
    float hloc[CH], cA[CH];
    float a = 1.f, hv = 0.f;
    int s0 = t * CH;
    #pragma unroll
    for (int j = 0; j < CH; j++) {
        int r = b*Ss + s0 + j;
        float dt = g_dt[r*Hh + h];
        float dA = expf(dt * Ah);
        float u  = dt * g_xin[r*Hh + h] * g_p[(size_t)r*TOT + 2*DI + Hh + h*Nn + n];
        hv = dA * hv + u;
        a *= dA;
        hloc[j] = hv; cA[j] = a;
    }
    __shared__ float sA[256], sB[256];
    sA[t] = a; sB[t] = hv;
    __syncthreads();
    for (int off = 1; off < 256; off <<= 1) {
        float pa = 0.f, pb = 0.f;
        if (t >= off) { pa = sA[t - off]; pb = sB[t - off]; }
        __syncthreads();
        if (t >= off) { sB[t] = sA[t] * pb + sB[t]; sA[t] = sA[t] * pa; }
        __syncthreads();
    }
    float hin = (t == 0) ? 0.f : sB[t - 1];
    #pragma unroll
    for (int j = 0; j < CH; j++) {
        int r = b*Ss + s0 + j;
        g_hs[((size_t)r*Hh + h) * Nn + n] = hloc[j] + cA[j] * hin;
    }
}

// ---------------- y = sum_n h*C ----------------
__global__ void k_yred() {
    int i = blockIdx.x * blockDim.x + threadIdx.x;
    if (i >= ROWS * Hh) return;
    int h = i % Hh;
    int r = i / Hh;
    const float* hs = &g_hs[(size_t)i * Nn];
    const float* Cp = &g_p[(size_t)r*TOT + 2*DI + Hh + Hh*Nn + h*Nn];
    float s = 0.f;
    #pragma unroll
    for (int n = 0; n < Nn; n++) s += hs[n] * Cp[n];
    g_y[i] = s;
}

// ---------------- y_proj + gate ----------------
__global__ void k_ymix(const float* __restrict__ yw) {
    int i = blockIdx.x * blockDim.x + threadIdx.x;
    if (i >= ROWS * DI) return;
    int c = i % DI;
    int r = i / DI;
    float s = 0.f;
    #pragma unroll
    for (int h = 0; h < Hh; h++) s += g_y[r*Hh + h] * yw[c*Hh + h];
    float z = g_p[(size_t)r*TOT + c];
    g_yi[i] = s * siluf(z);
}

// ---------------- final layernorm ----------------
__global__ void k_ln(const float* __restrict__ ln_w, const float* __restrict__ ln_b) {
    __shared__ float sh[256];
    int r = blockIdx.x, t = threadIdx.x;
    float v0 = g_x[(size_t)r*Dd + t];
    float v1 = g_x[(size_t)r*Dd + t + 256];
    float mu = blockReduceSum256(v0 + v1, sh) / (float)Dd;
    float d0 = v0 - mu, d1 = v1 - mu;
    float var = blockReduceSum256(d0*d0 + d1*d1, sh) / (float)Dd;
    float sc = rsqrtf(var + 1e-5f);
    g_xn[(size_t)r*Dd + t]       = d0 * sc * ln_w[t]       + ln_b[t];
    g_xn[(size_t)r*Dd + t + 256] = d1 * sc * ln_w[t + 256] + ln_b[t + 256];
}

// ---------------- launch ----------------
extern "C" void kernel_launch(void* const* d_in, const int* in_sizes, int n_in,
                              void* d_out, int out_size) {
    const int*   tok    = (const int*)  d_in[0];
    const float* emb    = (const float*)d_in[1];
    const float* rms_w  = (const float*)d_in[2];
    const float* in_w   = (const float*)d_in[3];
    const float* conv_w = (const float*)d_in[4];
    const float* dt_b   = (const float*)d_in[5];
    const float* A_log  = (const float*)d_in[6];
    const float* y_w    = (const float*)d_in[7];
    const float* out_w  = (const float*)d_in[8];
    const float* ln_w   = (const float*)d_in[9];
    const float* ln_b   = (const float*)d_in[10];
    const float* head_w = (const float*)d_in[11];
    const float* head_b = (const float*)d_in[12];
    float* out = (float*)d_out;

    float *p_x, *p_xn, *p_yi, *p_p;
    cudaGetSymbolAddress((void**)&p_x,  g_x);
    cudaGetSymbolAddress((void**)&p_xn, g_xn);
    cudaGetSymbolAddress((void**)&p_yi, g_yi);
    cudaGetSymbolAddress((void**)&p_p,  g_p);
    __nv_bfloat16 *p_ahi, *p_alo, *p_whi, *p_wlo;
    cudaGetSymbolAddress((void**)&p_ahi, g_ahi);
    cudaGetSymbolAddress((void**)&p_alo, g_alo);
    cudaGetSymbolAddress((void**)&p_whi, g_whi);
    cudaGetSymbolAddress((void**)&p_wlo, g_wlo);

    static int smem_set = 0;
    if (!smem_set) {
        cudaFuncSetAttribute(k_gemm_mma<0,0>, cudaFuncAttributeMaxDynamicSharedMemorySize, GEMM_SMEM);
        cudaFuncSetAttribute(k_gemm_mma<1,0>, cudaFuncAttributeMaxDynamicSharedMemorySize, GEMM_SMEM);
        cudaFuncSetAttribute(k_gemm_mma<0,1>, cudaFuncAttributeMaxDynamicSharedMemorySize, GEMM_SMEM);
        smem_set = 1;
    }

    k_embed<<<(ROWS*Dd + 255)/256, 256>>>(tok, emb);

    for (int L = 0; L < NLAYERS; L++) {
        k_rms<<<ROWS, 256>>>(rms_w + (size_t)L*Dd);

        k_cvt<<<(ROWS*Dd/4 + 255)/256, 256>>>(p_xn, p_ahi, p_alo, ROWS*Dd);
        k_cvt<<<(TOT*Dd/4 + 255)/256, 256>>>(in_w + (size_t)L*TOT*Dd, p_whi, p_wlo, TOT*Dd);

        // p = xn @ in_w^T  (M=4096, N=2312, K=512)
        {
            dim3 g((TOT + 127)/128, ROWS/128);
            k_gemm_mma<0,0><<<g, 256, GEMM_SMEM>>>(p_ahi, p_alo, p_whi, p_wlo,
                                                   nullptr, nullptr, p_p, TOT, Dd);
        }

        k_conv<<<(ROWS*DI + 255)/256, 256>>>(conv_w + (size_t)L*DI*Kk);
        k_dtx <<<ROWS, 256>>>(dt_b + (size_t)L*Hh);
        k_scan<<<Bb*Hh*Nn, 256>>>(A_log + (size_t)L*Hh);
        k_yred<<<(ROWS*Hh + 255)/256, 256>>>();
        k_ymix<<<(ROWS*DI + 255)/256, 256>>>(y_w + (size_t)L*DI*Hh);

        // x = yi @ out_w^T + x  (M=4096, N=512, K=1024)
        k_cvt<<<(ROWS*DI/4 + 255)/256, 256>>>(p_yi, p_ahi, p_alo, ROWS*DI);
        k_cvt<<<(Dd*DI/4 + 255)/256, 256>>>(out_w + (size_t)L*Dd*DI, p_whi, p_wlo, Dd*DI);
        {
            dim3 g(Dd/128, ROWS/128);
            k_gemm_mma<1,0><<<g, 256, GEMM_SMEM>>>(p_ahi, p_alo, p_whi, p_wlo,
                                                   p_x, nullptr, p_x, Dd, DI);
        }
    }

    k_ln<<<ROWS, 256>>>(ln_w, ln_b);

    // out = xn @ head_w^T + head_b  (M=4096, N=32000, K=512)
    k_cvt<<<(ROWS*Dd/4 + 255)/256, 256>>>(p_xn, p_ahi, p_alo, ROWS*Dd);
    k_cvt<<<((int)((size_t)Vv*Dd/4) + 255)/256, 256>>>(head_w, p_whi, p_wlo, Vv*Dd);
    {
        dim3 g(Vv/128, ROWS/128);
        k_gemm_mma<0,1><<<g, 256, GEMM_SMEM>>>(p_ahi, p_alo, p_whi, p_wlo,
                                               nullptr, head_b, out, Vv, Dd);
    }
}

// round 7
// speedup vs baseline: 2.4506x; 1.0924x over previous
#include <cuda_runtime.h>
#include <cuda_bf16.h>
#include <math.h>
#include <stdint.h>

// ---------------- problem constants ----------------
#define Bb 2
#define Ss 2048
#define Dd 512
#define NLAYERS 6
#define DI 1024
#define Hh 8
#define Nn 16
#define Kk 4
#define Vv 32000
#define TOT (2*DI + Hh + 2*Hh*Nn)   // 2312
#define ROWS (Bb*Ss)                // 4096

// ---------------- scratch (static device globals; no allocation) ----------------
__device__ float g_x [ROWS*Dd];        // residual stream
__device__ float g_p [ROWS*TOT];       // in_proj output
__device__ float g_dt[ROWS*Hh];
__device__ float g_xin[ROWS*Hh];
__device__ float g_hs[ROWS*Hh*Nn];
__device__ float g_y [ROWS*Hh];
// bf16 split buffers (activations + weights)
__device__ __align__(128) __nv_bfloat16 g_ahi[ROWS*DI];
__device__ __align__(128) __nv_bfloat16 g_alo[ROWS*DI];
__device__ __align__(128) __nv_bfloat16 g_whi[(size_t)Vv*Dd];
__device__ __align__(128) __nv_bfloat16 g_wlo[(size_t)Vv*Dd];

// ---------------- small helpers ----------------
__device__ __forceinline__ float blockReduceSum256(float v, float* sh) {
    int t = threadIdx.x;
    sh[t] = v; __syncthreads();
    #pragma unroll
    for (int o = 128; o > 0; o >>= 1) {
        if (t < o) sh[t] += sh[t + o];
        __syncthreads();
    }
    float r = sh[0];
    __syncthreads();
    return r;
}
__device__ __forceinline__ float siluf(float v) { return v / (1.f + expf(-v)); }
__device__ __forceinline__ float softplusf(float v) {
    return (v > 0.f) ? (v + log1pf(expf(-v))) : log1pf(expf(v));
}
__device__ __forceinline__ void split_bf16(float x, __nv_bfloat16& h, __nv_bfloat16& l) {
    h = __float2bfloat16(x);
    l = __float2bfloat16(x - __bfloat162float(h));
}

// ---------------- MMA primitives (arch-neutral, sm_80+) ----------------
__device__ __forceinline__ void cp16(uint32_t s, const void* g, uint32_t sz) {
    asm volatile("cp.async.cg.shared.global [%0], [%1], 16, %2;"
                 :: "r"(s), "l"(g), "r"(sz) : "memory");
}
__device__ __forceinline__ void cp_commit() {
    asm volatile("cp.async.commit_group;" ::: "memory");
}
__device__ __forceinline__ void cp_wait1() {
    asm volatile("cp.async.wait_group 1;" ::: "memory");
}
__device__ __forceinline__ void cp_wait0() {
    asm volatile("cp.async.wait_group 0;" ::: "memory");
}
__device__ __forceinline__ void ldm4(uint32_t* r, uint32_t a) {
    asm volatile("ldmatrix.sync.aligned.m8n8.x4.shared.b16 {%0,%1,%2,%3}, [%4];"
                 : "=r"(r[0]), "=r"(r[1]), "=r"(r[2]), "=r"(r[3]) : "r"(a));
}
__device__ __forceinline__ void mma16816(float* d, const uint32_t* a,
                                         uint32_t b0, uint32_t b1) {
    asm volatile("mma.sync.aligned.m16n8k16.row.col.f32.bf16.bf16.f32 "
                 "{%0,%1,%2,%3}, {%4,%5,%6,%7}, {%8,%9}, {%0,%1,%2,%3};"
                 : "+f"(d[0]), "+f"(d[1]), "+f"(d[2]), "+f"(d[3])
                 : "r"(a[0]), "r"(a[1]), "r"(a[2]), "r"(a[3]), "r"(b0), "r"(b1));
}

// ---------------- fp32 -> bf16 hi/lo split (weights) ----------------
__global__ void k_cvt(const float* __restrict__ src, __nv_bfloat16* __restrict__ hi,
                      __nv_bfloat16* __restrict__ lo, int n) {
    int i = (blockIdx.x * blockDim.x + threadIdx.x) * 4;
    if (i >= n) return;
    float4 v = *(const float4*)(src + i);
    __nv_bfloat16 h0, h1, h2, h3, l0, l1, l2, l3;
    split_bf16(v.x, h0, l0); split_bf16(v.y, h1, l1);
    split_bf16(v.z, h2, l2); split_bf16(v.w, h3, l3);
    ((__nv_bfloat162*)(hi + i))[0] = __halves2bfloat162(h0, h1);
    ((__nv_bfloat162*)(hi + i))[1] = __halves2bfloat162(h2, h3);
    ((__nv_bfloat162*)(lo + i))[0] = __halves2bfloat162(l0, l1);
    ((__nv_bfloat162*)(lo + i))[1] = __halves2bfloat162(l2, l3);
}

// ---------------- HMMA GEMM: C[M,N] = A[M,K] @ B[N,K]^T (+res)(+bias) ----------------
#define TILE_B   10240              // 128 rows * 80 B
#define STAGE_B  (4*TILE_B)
#define GEMM_SMEM (2*STAGE_B)       // 81920

template<int ADD_RES, int ADD_BIAS>
__global__ void __launch_bounds__(256)
k_gemm_mma(const __nv_bfloat16* __restrict__ Ahi, const __nv_bfloat16* __restrict__ Alo,
           const __nv_bfloat16* __restrict__ Bhi, const __nv_bfloat16* __restrict__ Blo,
           const float* __restrict__ Res, const float* __restrict__ bias,
           float* __restrict__ C, int Nd, int Kd)
{
    extern __shared__ char smem[];
    const uint32_t sbase = (uint32_t)__cvta_generic_to_shared(smem);

    int tid = threadIdx.x, wid = tid >> 5, lane = tid & 31;
    int bm = blockIdx.y * 128, bn = blockIdx.x * 128;
    int wm = (wid >> 2) * 64, wn = (wid & 3) * 32;

    float acc[4][4][4];
    #pragma unroll
    for (int i = 0; i < 4; i++)
        #pragma unroll
        for (int j = 0; j < 4; j++)
            #pragma unroll
            for (int q = 0; q < 4; q++) acc[i][j][q] = 0.f;

    const int nch = Kd >> 5;

    auto load_stage = [&](int stage, int ch) {
        uint32_t sb = sbase + stage * STAGE_B;
        int k0 = ch << 5;
        #pragma unroll
        for (int j = 0; j < 2; j++) {
            int c = tid + j * 256;
            int row = c >> 2, q = c & 3;
            uint32_t so = (uint32_t)(row * 80 + q * 16);
            size_t ga = (size_t)(bm + row) * Kd + k0 + q * 8;
            cp16(sb + 0*TILE_B + so, Ahi + ga, 16);
            cp16(sb + 1*TILE_B + so, Alo + ga, 16);
            int brow = bn + row;
            uint32_t sz = (brow < Nd) ? 16u : 0u;
            int brc = brow < Nd ? brow : (Nd - 1);
            size_t gb = (size_t)brc * Kd + k0 + q * 8;
            cp16(sb + 2*TILE_B + so, Bhi + gb, sz);
            cp16(sb + 3*TILE_B + so, Blo + gb, sz);
        }
        cp_commit();
    };

    load_stage(0, 0);

    for (int ch = 0; ch < nch; ch++) {
        if (ch + 1 < nch) { load_stage((ch + 1) & 1, ch + 1); cp_wait1(); }
        else               cp_wait0();
        __syncthreads();

        uint32_t sb = sbase + (ch & 1) * STAGE_B;
        uint32_t sAh = sb, sAl = sb + TILE_B, sBh = sb + 2*TILE_B, sBl = sb + 3*TILE_B;

        #pragma unroll
        for (int ks = 0; ks < 2; ks++) {
            uint32_t aH[4][4], aL[4][4];
            int arow = (lane & 15);
            int acb  = ks * 32 + ((lane & 16) ? 16 : 0);
            #pragma unroll
            for (int mt = 0; mt < 4; mt++) {
                uint32_t ao = (uint32_t)((wm + mt*16 + arow) * 80 + acb);
                ldm4(aH[mt], sAh + ao);
                ldm4(aL[mt], sAl + ao);
            }
            int brow = ((lane & 16) ? 8 : 0) + (lane & 7);
            int bcb  = ks * 32 + ((lane & 8) ? 16 : 0);
            #pragma unroll
            for (int ntp = 0; ntp < 2; ntp++) {
                uint32_t bo = (uint32_t)((wn + ntp*16 + brow) * 80 + bcb);
                uint32_t bh[4], bl[4];
                ldm4(bh, sBh + bo);
                ldm4(bl, sBl + bo);
                #pragma unroll
                for (int mt = 0; mt < 4; mt++) {
                    int nt0 = ntp * 2;
                    mma16816(acc[mt][nt0],   aH[mt], bh[0], bh[1]);
                    mma16816(acc[mt][nt0],   aH[mt], bl[0], bl[1]);
                    mma16816(acc[mt][nt0],   aL[mt], bh[0], bh[1]);
                    mma16816(acc[mt][nt0+1], aH[mt], bh[2], bh[3]);
                    mma16816(acc[mt][nt0+1], aH[mt], bl[2], bl[3]);
                    mma16816(acc[mt][nt0+1], aL[mt], bh[2], bh[3]);
                }
            }
        }
        __syncthreads();
    }

    #pragma unroll
    for (int mt = 0; mt < 4; mt++) {
        int r0 = bm + wm + mt*16 + (lane >> 2);
        #pragma unroll
        for (int nt = 0; nt < 4; nt++) {
            int n = bn + wn + nt*8 + (lane & 3) * 2;
            if (n < Nd) {
                float2 v0 = make_float2(acc[mt][nt][0], acc[mt][nt][1]);
                float2 v1 = make_float2(acc[mt][nt][2], acc[mt][nt][3]);
                if (ADD_BIAS) {
                    float2 bv = *(const float2*)(bias + n);
                    v0.x += bv.x; v0.y += bv.y; v1.x += bv.x; v1.y += bv.y;
                }
                if (ADD_RES) {
                    float2 r0v = *(const float2*)(Res + (size_t)r0 * Nd + n);
                    float2 r1v = *(const float2*)(Res + (size_t)(r0+8) * Nd + n);
                    v0.x += r0v.x; v0.y += r0v.y; v1.x += r1v.x; v1.y += r1v.y;
                }
                *(float2*)(C + (size_t)r0 * Nd + n)     = v0;
                *(float2*)(C + (size_t)(r0+8) * Nd + n) = v1;
            }
        }
    }
}

// ---------------- embedding gather ----------------
__global__ void k_embed(const int* __restrict__ tok, const float* __restrict__ emb) {
    int i = blockIdx.x * blockDim.x + threadIdx.x;
    if (i < ROWS * Dd) {
        int r = i / Dd, d = i - r * Dd;
        g_x[i] = emb[(size_t)tok[r] * Dd + d];
    }
}

// ---------------- rmsnorm fused with bf16 hi/lo split ----------------
__global__ void k_rms_cvt(const float* __restrict__ rms_w) {
    __shared__ float sh[256];
    int r = blockIdx.x, t = threadIdx.x;
    float v0 = g_x[(size_t)r*Dd + t];
    float v1 = g_x[(size_t)r*Dd + t + 256];
    float ss = blockReduceSum256(v0*v0 + v1*v1, sh);
    float sc = rsqrtf(ss / (float)Dd + 1e-6f);
    float o0 = v0 * sc * rms_w[t];
    float o1 = v1 * sc * rms_w[t + 256];
    __nv_bfloat16 h, l;
    split_bf16(o0, h, l);
    g_ahi[(size_t)r*Dd + t] = h; g_alo[(size_t)r*Dd + t] = l;
    split_bf16(o1, h, l);
    g_ahi[(size_t)r*Dd + t + 256] = h; g_alo[(size_t)r*Dd + t + 256] = l;
}

// ---------------- fused conv+SiLU+head-mean+dt-softplus (g_xc eliminated) ----------------
// one block per row; warp w handles head w (channels w*128 .. w*128+127)
__global__ __launch_bounds__(256)
void k_convdtx(const float* __restrict__ cw, const float* __restrict__ dtb) {
    int r = blockIdx.x;
    int s = r % Ss, b = r / Ss;
    int w = threadIdx.x >> 5, lane = threadIdx.x & 31;
    float sum = 0.f;
    #pragma unroll
    for (int j = 0; j < 4; j++) {
        int c = w * 128 + lane + 32 * j;
        float4 cv = ((const float4*)cw)[c];
        float acc = 0.f;
        const float* base = &g_p[(size_t)(b*Ss) * TOT + DI + c];
        if (s >= 3) {
            acc = base[(size_t)(s-3)*TOT] * cv.x + base[(size_t)(s-2)*TOT] * cv.y
                + base[(size_t)(s-1)*TOT] * cv.z + base[(size_t)s*TOT] * cv.w;
        } else {
            #pragma unroll
            for (int k = 0; k < 4; k++) {
                int sp = s + k - 3;
                if (sp >= 0) acc += base[(size_t)sp*TOT] * ((const float*)&cv)[k];
            }
        }
        sum += siluf(acc);
    }
    #pragma unroll
    for (int o = 16; o > 0; o >>= 1) sum += __shfl_xor_sync(0xffffffffu, sum, o);
    if (lane == 0) {
        g_xin[r*Hh + w] = sum * (1.f / 128.f);
        float dt = g_p[(size_t)r*TOT + 2*DI + w] + dtb[w];
        g_dt[r*Hh + w] = softplusf(dt);
    }
}

// ---------------- parallel associative scan ----------------
__global__ __launch_bounds__(256)
void k_scan(const float* __restrict__ A_log) {
    const int CH = Ss / 256;
    int chain = blockIdx.x;
    int n = chain % Nn;
    int h = (chain / Nn) % Hh;
    int b = chain / (Nn * Hh);
    float Ah = -expf(A_log[h]);

    int t = threadIdx.x;
    float hloc[CH], cA[CH];
    float a = 1.f, hv = 0.f;
    int s0 = t * CH;
    #pragma unroll
    for (int j = 0; j < CH; j++) {
        int r = b*Ss + s0 + j;
        float dt = g_dt[r*Hh + h];
        float dA = expf(dt * Ah);
        float u  = dt * g_xin[r*Hh + h] * g_p[(size_t)r*TOT + 2*DI + Hh + h*Nn + n];
        hv = dA * hv + u;
        a *= dA;
        hloc[j] = hv; cA[j] = a;
    }
    __shared__ float sA[256], sB[256];
    sA[t] = a; sB[t] = hv;
    __syncthreads();
    for (int off = 1; off < 256; off <<= 1) {
        float pa = 0.f, pb = 0.f;
        if (t >= off) { pa = sA[t - off]; pb = sB[t - off]; }
        __syncthreads();
        if (t >= off) { sB[t] = sA[t] * pb + sB[t]; sA[t] = sA[t] * pa; }
        __syncthreads();
    }
    float hin = (t == 0) ? 0.f : sB[t - 1];
    #pragma unroll
    for (int j = 0; j < CH; j++) {
        int r = b*Ss + s0 + j;
        g_hs[((size_t)r*Hh + h) * Nn + n] = hloc[j] + cA[j] * hin;
    }
}

// ---------------- y = sum_n h*C ----------------
__global__ void k_yred() {
    int i = blockIdx.x * blockDim.x + threadIdx.x;
    if (i >= ROWS * Hh) return;
    int h = i % Hh;
    int r = i / Hh;
    const float* hs = &g_hs[(size_t)i * Nn];
    const float* Cp = &g_p[(size_t)r*TOT + 2*DI + Hh + Hh*Nn + h*Nn];
    float s = 0.f;
    #pragma unroll
    for (int n = 0; n < Nn; n++) s += hs[n] * Cp[n];
    g_y[i] = s;
}

// ---------------- y_proj + gate fused with bf16 hi/lo split ----------------
__global__ void k_ymix_cvt(const float* __restrict__ yw) {
    int i = blockIdx.x * blockDim.x + threadIdx.x;
    if (i >= ROWS * DI) return;
    int c = i % DI;
    int r = i / DI;
    float4 w0 = ((const float4*)yw)[c*2];
    float4 w1 = ((const float4*)yw)[c*2 + 1];
    const float* y = &g_y[r*Hh];
    float s = y[0]*w0.x + y[1]*w0.y + y[2]*w0.z + y[3]*w0.w
            + y[4]*w1.x + y[5]*w1.y + y[6]*w1.z + y[7]*w1.w;
    float z = g_p[(size_t)r*TOT + c];
    float v = s * siluf(z);
    __nv_bfloat16 h, l;
    split_bf16(v, h, l);
    g_ahi[i] = h; g_alo[i] = l;
}

// ---------------- final layernorm fused with bf16 hi/lo split ----------------
__global__ void k_ln_cvt(const float* __restrict__ ln_w, const float* __restrict__ ln_b) {
    __shared__ float sh[256];
    int r = blockIdx.x, t = threadIdx.x;
    float v0 = g_x[(size_t)r*Dd + t];
    float v1 = g_x[(size_t)r*Dd + t + 256];
    float mu = blockReduceSum256(v0 + v1, sh) / (float)Dd;
    float d0 = v0 - mu, d1 = v1 - mu;
    float var = blockReduceSum256(d0*d0 + d1*d1, sh) / (float)Dd;
    float sc = rsqrtf(var + 1e-5f);
    float o0 = d0 * sc * ln_w[t]       + ln_b[t];
    float o1 = d1 * sc * ln_w[t + 256] + ln_b[t + 256];
    __nv_bfloat16 h, l;
    split_bf16(o0, h, l);
    g_ahi[(size_t)r*Dd + t] = h; g_alo[(size_t)r*Dd + t] = l;
    split_bf16(o1, h, l);
    g_ahi[(size_t)r*Dd + t + 256] = h; g_alo[(size_t)r*Dd + t + 256] = l;
}

// ---------------- launch ----------------
extern "C" void kernel_launch(void* const* d_in, const int* in_sizes, int n_in,
                              void* d_out, int out_size) {
    const int*   tok    = (const int*)  d_in[0];
    const float* emb    = (const float*)d_in[1];
    const float* rms_w  = (const float*)d_in[2];
    const float* in_w   = (const float*)d_in[3];
    const float* conv_w = (const float*)d_in[4];
    const float* dt_b   = (const float*)d_in[5];
    const float* A_log  = (const float*)d_in[6];
    const float* y_w    = (const float*)d_in[7];
    const float* out_w  = (const float*)d_in[8];
    const float* ln_w   = (const float*)d_in[9];
    const float* ln_b   = (const float*)d_in[10];
    const float* head_w = (const float*)d_in[11];
    const float* head_b = (const float*)d_in[12];
    float* out = (float*)d_out;

    float *p_x, *p_p;
    cudaGetSymbolAddress((void**)&p_x,  g_x);
    cudaGetSymbolAddress((void**)&p_p,  g_p);
    __nv_bfloat16 *p_ahi, *p_alo, *p_whi, *p_wlo;
    cudaGetSymbolAddress((void**)&p_ahi, g_ahi);
    cudaGetSymbolAddress((void**)&p_alo, g_alo);
    cudaGetSymbolAddress((void**)&p_whi, g_whi);
    cudaGetSymbolAddress((void**)&p_wlo, g_wlo);

    static int smem_set = 0;
    if (!smem_set) {
        cudaFuncSetAttribute(k_gemm_mma<0,0>, cudaFuncAttributeMaxDynamicSharedMemorySize, GEMM_SMEM);
        cudaFuncSetAttribute(k_gemm_mma<1,0>, cudaFuncAttributeMaxDynamicSharedMemorySize, GEMM_SMEM);
        cudaFuncSetAttribute(k_gemm_mma<0,1>, cudaFuncAttributeMaxDynamicSharedMemorySize, GEMM_SMEM);
        smem_set = 1;
    }

    k_embed<<<(ROWS*Dd + 255)/256, 256>>>(tok, emb);

    for (int L = 0; L < NLAYERS; L++) {
        // rmsnorm + activation split
        k_rms_cvt<<<ROWS, 256>>>(rms_w + (size_t)L*Dd);
        // weight split
        k_cvt<<<(TOT*Dd/4 + 255)/256, 256>>>(in_w + (size_t)L*TOT*Dd, p_whi, p_wlo, TOT*Dd);

        // p = xn @ in_w^T  (M=4096, N=2312, K=512)
        {
            dim3 g((TOT + 127)/128, ROWS/128);
            k_gemm_mma<0,0><<<g, 256, GEMM_SMEM>>>(p_ahi, p_alo, p_whi, p_wlo,
                                                   nullptr, nullptr, p_p, TOT, Dd);
        }

        k_convdtx<<<ROWS, 256>>>(conv_w + (size_t)L*DI*Kk, dt_b + (size_t)L*Hh);
        k_scan<<<Bb*Hh*Nn, 256>>>(A_log + (size_t)L*Hh);
        k_yred<<<(ROWS*Hh + 255)/256, 256>>>();
        k_ymix_cvt<<<(ROWS*DI + 255)/256, 256>>>(y_w + (size_t)L*DI*Hh);

        // x = yi @ out_w^T + x  (M=4096, N=512, K=1024)
        k_cvt<<<(Dd*DI/4 + 255)/256, 256>>>(out_w + (size_t)L*Dd*DI, p_whi, p_wlo, Dd*DI);
        {
            dim3 g(Dd/128, ROWS/128);
            k_gemm_mma<1,0><<<g, 256, GEMM_SMEM>>>(p_ahi, p_alo, p_whi, p_wlo,
                                                   p_x, nullptr, p_x, Dd, DI);
        }
    }

    k_ln_cvt<<<ROWS, 256>>>(ln_w, ln_b);

    // out = xn @ head_w^T + head_b  (M=4096, N=32000, K=512)
    k_cvt<<<((int)((size_t)Vv*Dd/4) + 255)/256, 256>>>(head_w, p_whi, p_wlo, Vv*Dd);
    {
        dim3 g(Vv/128, ROWS/128);
        k_gemm_mma<0,1><<<g, 256, GEMM_SMEM>>>(p_ahi, p_alo, p_whi, p_wlo,
                                               nullptr, head_b, out, Vv, Dd);
    }
}

// round 8
// speedup vs baseline: 2.6011x; 1.0614x over previous
#include <cuda_runtime.h>
#include <cuda_bf16.h>
#include <math.h>
#include <stdint.h>

// ---------------- problem constants ----------------
#define Bb 2
#define Ss 2048
#define Dd 512
#define NLAYERS 6
#define DI 1024
#define Hh 8
#define Nn 16
#define Kk 4
#define Vv 32000
#define TOT (2*DI + Hh + 2*Hh*Nn)   // 2312
#define ROWS (Bb*Ss)                // 4096

// ---------------- scratch (static device globals; no allocation) ----------------
__device__ float g_x [ROWS*Dd];        // residual stream
__device__ float g_p [ROWS*TOT];       // in_proj output
__device__ float g_dt[ROWS*Hh];
__device__ float g_xin[ROWS*Hh];
__device__ float g_hs[ROWS*Hh*Nn];
__device__ float g_y [ROWS*Hh];
// bf16 split buffers (activations + weights)
__device__ __align__(128) __nv_bfloat16 g_ahi[ROWS*DI];
__device__ __align__(128) __nv_bfloat16 g_alo[ROWS*DI];
__device__ __align__(128) __nv_bfloat16 g_whi[(size_t)Vv*Dd];
__device__ __align__(128) __nv_bfloat16 g_wlo[(size_t)Vv*Dd];

// ---------------- small helpers ----------------
__device__ __forceinline__ float blockReduceSum256(float v, float* sh) {
    int t = threadIdx.x;
    sh[t] = v; __syncthreads();
    #pragma unroll
    for (int o = 128; o > 0; o >>= 1) {
        if (t < o) sh[t] += sh[t + o];
        __syncthreads();
    }
    float r = sh[0];
    __syncthreads();
    return r;
}
__device__ __forceinline__ float siluf(float v) { return v / (1.f + expf(-v)); }
__device__ __forceinline__ float softplusf(float v) {
    return (v > 0.f) ? (v + log1pf(expf(-v))) : log1pf(expf(v));
}
__device__ __forceinline__ void split_bf16(float x, __nv_bfloat16& h, __nv_bfloat16& l) {
    h = __float2bfloat16(x);
    l = __float2bfloat16(x - __bfloat162float(h));
}

// ---------------- MMA primitives (arch-neutral, sm_80+) ----------------
__device__ __forceinline__ void cp16(uint32_t s, const void* g, uint32_t sz) {
    asm volatile("cp.async.cg.shared.global [%0], [%1], 16, %2;"
                 :: "r"(s), "l"(g), "r"(sz) : "memory");
}
__device__ __forceinline__ void cp_commit() {
    asm volatile("cp.async.commit_group;" ::: "memory");
}
__device__ __forceinline__ void cp_wait1() {
    asm volatile("cp.async.wait_group 1;" ::: "memory");
}
__device__ __forceinline__ void cp_wait0() {
    asm volatile("cp.async.wait_group 0;" ::: "memory");
}
__device__ __forceinline__ void ldm4(uint32_t* r, uint32_t a) {
    asm volatile("ldmatrix.sync.aligned.m8n8.x4.shared.b16 {%0,%1,%2,%3}, [%4];"
                 : "=r"(r[0]), "=r"(r[1]), "=r"(r[2]), "=r"(r[3]) : "r"(a));
}
__device__ __forceinline__ void mma16816(float* d, const uint32_t* a,
                                         uint32_t b0, uint32_t b1) {
    asm volatile("mma.sync.aligned.m16n8k16.row.col.f32.bf16.bf16.f32 "
                 "{%0,%1,%2,%3}, {%4,%5,%6,%7}, {%8,%9}, {%0,%1,%2,%3};"
                 : "+f"(d[0]), "+f"(d[1]), "+f"(d[2]), "+f"(d[3])
                 : "r"(a[0]), "r"(a[1]), "r"(a[2]), "r"(a[3]), "r"(b0), "r"(b1));
}

// ---------------- fp32 -> bf16 hi/lo split (weights) ----------------
__global__ void k_cvt(const float* __restrict__ src, __nv_bfloat16* __restrict__ hi,
                      __nv_bfloat16* __restrict__ lo, int n) {
    int i = (blockIdx.x * blockDim.x + threadIdx.x) * 4;
    if (i >= n) return;
    float4 v = *(const float4*)(src + i);
    __nv_bfloat16 h0, h1, h2, h3, l0, l1, l2, l3;
    split_bf16(v.x, h0, l0); split_bf16(v.y, h1, l1);
    split_bf16(v.z, h2, l2); split_bf16(v.w, h3, l3);
    ((__nv_bfloat162*)(hi + i))[0] = __halves2bfloat162(h0, h1);
    ((__nv_bfloat162*)(hi + i))[1] = __halves2bfloat162(h2, h3);
    ((__nv_bfloat162*)(lo + i))[0] = __halves2bfloat162(l0, l1);
    ((__nv_bfloat162*)(lo + i))[1] = __halves2bfloat162(l2, l3);
}

// ---------------- HMMA GEMM: C[M,N] = A[M,K] @ B[N,K]^T (+res)(+bias) ----------------
// 2 CTAs/SM (reg cap 128): B fragments held per k-step, A fragments streamed.
#define TILE_B   10240              // 128 rows * 80 B
#define STAGE_B  (4*TILE_B)
#define GEMM_SMEM (2*STAGE_B)       // 81920

template<int ADD_RES, int ADD_BIAS>
__global__ void __launch_bounds__(256, 2)
k_gemm_mma(const __nv_bfloat16* __restrict__ Ahi, const __nv_bfloat16* __restrict__ Alo,
           const __nv_bfloat16* __restrict__ Bhi, const __nv_bfloat16* __restrict__ Blo,
           const float* __restrict__ Res, const float* __restrict__ bias,
           float* __restrict__ C, int Nd, int Kd)
{
    extern __shared__ char smem[];
    const uint32_t sbase = (uint32_t)__cvta_generic_to_shared(smem);

    int tid = threadIdx.x, wid = tid >> 5, lane = tid & 31;
    int bm = blockIdx.y * 128, bn = blockIdx.x * 128;
    int wm = (wid >> 2) * 64, wn = (wid & 3) * 32;

    float acc[4][4][4];
    #pragma unroll
    for (int i = 0; i < 4; i++)
        #pragma unroll
        for (int j = 0; j < 4; j++)
            #pragma unroll
            for (int q = 0; q < 4; q++) acc[i][j][q] = 0.f;

    const int nch = Kd >> 5;

    auto load_stage = [&](int stage, int ch) {
        uint32_t sb = sbase + stage * STAGE_B;
        int k0 = ch << 5;
        #pragma unroll
        for (int j = 0; j < 2; j++) {
            int c = tid + j * 256;
            int row = c >> 2, q = c & 3;
            uint32_t so = (uint32_t)(row * 80 + q * 16);
            size_t ga = (size_t)(bm + row) * Kd + k0 + q * 8;
            cp16(sb + 0*TILE_B + so, Ahi + ga, 16);
            cp16(sb + 1*TILE_B + so, Alo + ga, 16);
            int brow = bn + row;
            uint32_t sz = (brow < Nd) ? 16u : 0u;
            int brc = brow < Nd ? brow : (Nd - 1);
            size_t gb = (size_t)brc * Kd + k0 + q * 8;
            cp16(sb + 2*TILE_B + so, Bhi + gb, sz);
            cp16(sb + 3*TILE_B + so, Blo + gb, sz);
        }
        cp_commit();
    };

    load_stage(0, 0);

    for (int ch = 0; ch < nch; ch++) {
        if (ch + 1 < nch) { load_stage((ch + 1) & 1, ch + 1); cp_wait1(); }
        else               cp_wait0();
        __syncthreads();

        uint32_t sb = sbase + (ch & 1) * STAGE_B;
        uint32_t sAh = sb, sAl = sb + TILE_B, sBh = sb + 2*TILE_B, sBl = sb + 3*TILE_B;

        #pragma unroll
        for (int ks = 0; ks < 2; ks++) {
            // B fragments for both n-subtiles first (held across the mt loop)
            uint32_t bh[2][4], bl[2][4];
            int brow = ((lane & 16) ? 8 : 0) + (lane & 7);
            int bcb  = ks * 32 + ((lane & 8) ? 16 : 0);
            #pragma unroll
            for (int ntp = 0; ntp < 2; ntp++) {
                uint32_t bo = (uint32_t)((wn + ntp*16 + brow) * 80 + bcb);
                ldm4(bh[ntp], sBh + bo);
                ldm4(bl[ntp], sBl + bo);
            }
            // stream A fragments per 16-row subtile
            int arow = (lane & 15);
            int acb  = ks * 32 + ((lane & 16) ? 16 : 0);
            #pragma unroll
            for (int mt = 0; mt < 4; mt++) {
                uint32_t aH[4], aL[4];
                uint32_t ao = (uint32_t)((wm + mt*16 + arow) * 80 + acb);
                ldm4(aH, sAh + ao);
                ldm4(aL, sAl + ao);
                #pragma unroll
                for (int ntp = 0; ntp < 2; ntp++) {
                    int nt0 = ntp * 2;
                    mma16816(acc[mt][nt0],   aH, bh[ntp][0], bh[ntp][1]);
                    mma16816(acc[mt][nt0],   aH, bl[ntp][0], bl[ntp][1]);
                    mma16816(acc[mt][nt0],   aL, bh[ntp][0], bh[ntp][1]);
                    mma16816(acc[mt][nt0+1], aH, bh[ntp][2], bh[ntp][3]);
                    mma16816(acc[mt][nt0+1], aH, bl[ntp][2], bl[ntp][3]);
                    mma16816(acc[mt][nt0+1], aL, bh[ntp][2], bh[ntp][3]);
                }
            }
        }
        __syncthreads();
    }

    #pragma unroll
    for (int mt = 0; mt < 4; mt++) {
        int r0 = bm + wm + mt*16 + (lane >> 2);
        #pragma unroll
        for (int nt = 0; nt < 4; nt++) {
            int n = bn + wn + nt*8 + (lane & 3) * 2;
            if (n < Nd) {
                float2 v0 = make_float2(acc[mt][nt][0], acc[mt][nt][1]);
                float2 v1 = make_float2(acc[mt][nt][2], acc[mt][nt][3]);
                if (ADD_BIAS) {
                    float2 bv = *(const float2*)(bias + n);
                    v0.x += bv.x; v0.y += bv.y; v1.x += bv.x; v1.y += bv.y;
                }
                if (ADD_RES) {
                    float2 r0v = *(const float2*)(Res + (size_t)r0 * Nd + n);
                    float2 r1v = *(const float2*)(Res + (size_t)(r0+8) * Nd + n);
                    v0.x += r0v.x; v0.y += r0v.y; v1.x += r1v.x; v1.y += r1v.y;
                }
                *(float2*)(C + (size_t)r0 * Nd + n)     = v0;
                *(float2*)(C + (size_t)(r0+8) * Nd + n) = v1;
            }
        }
    }
}

// ---------------- embedding gather ----------------
__global__ void k_embed(const int* __restrict__ tok, const float* __restrict__ emb) {
    int i = blockIdx.x * blockDim.x + threadIdx.x;
    if (i < ROWS * Dd) {
        int r = i / Dd, d = i - r * Dd;
        g_x[i] = emb[(size_t)tok[r] * Dd + d];
    }
}

// ---------------- rmsnorm fused with bf16 hi/lo split ----------------
__global__ void k_rms_cvt(const float* __restrict__ rms_w) {
    __shared__ float sh[256];
    int r = blockIdx.x, t = threadIdx.x;
    float v0 = g_x[(size_t)r*Dd + t];
    float v1 = g_x[(size_t)r*Dd + t + 256];
    float ss = blockReduceSum256(v0*v0 + v1*v1, sh);
    float sc = rsqrtf(ss / (float)Dd + 1e-6f);
    float o0 = v0 * sc * rms_w[t];
    float o1 = v1 * sc * rms_w[t + 256];
    __nv_bfloat16 h, l;
    split_bf16(o0, h, l);
    g_ahi[(size_t)r*Dd + t] = h; g_alo[(size_t)r*Dd + t] = l;
    split_bf16(o1, h, l);
    g_ahi[(size_t)r*Dd + t + 256] = h; g_alo[(size_t)r*Dd + t + 256] = l;
}

// ---------------- fused conv+SiLU+head-mean+dt-softplus ----------------
__global__ __launch_bounds__(256)
void k_convdtx(const float* __restrict__ cw, const float* __restrict__ dtb) {
    int r = blockIdx.x;
    int s = r % Ss, b = r / Ss;
    int w = threadIdx.x >> 5, lane = threadIdx.x & 31;
    float sum = 0.f;
    #pragma unroll
    for (int j = 0; j < 4; j++) {
        int c = w * 128 + lane + 32 * j;
        float4 cv = ((const float4*)cw)[c];
        float acc = 0.f;
        const float* base = &g_p[(size_t)(b*Ss) * TOT + DI + c];
        if (s >= 3) {
            acc = base[(size_t)(s-3)*TOT] * cv.x + base[(size_t)(s-2)*TOT] * cv.y
                + base[(size_t)(s-1)*TOT] * cv.z + base[(size_t)s*TOT] * cv.w;
        } else {
            #pragma unroll
            for (int k = 0; k < 4; k++) {
                int sp = s + k - 3;
                if (sp >= 0) acc += base[(size_t)sp*TOT] * ((const float*)&cv)[k];
            }
        }
        sum += siluf(acc);
    }
    #pragma unroll
    for (int o = 16; o > 0; o >>= 1) sum += __shfl_xor_sync(0xffffffffu, sum, o);
    if (lane == 0) {
        g_xin[r*Hh + w] = sum * (1.f / 128.f);
        float dt = g_p[(size_t)r*TOT + 2*DI + w] + dtb[w];
        g_dt[r*Hh + w] = softplusf(dt);
    }
}

// ---------------- parallel associative scan ----------------
__global__ __launch_bounds__(256)
void k_scan(const float* __restrict__ A_log) {
    const int CH = Ss / 256;
    int chain = blockIdx.x;
    int n = chain % Nn;
    int h = (chain / Nn) % Hh;
    int b = chain / (Nn * Hh);
    float Ah = -expf(A_log[h]);

    int t = threadIdx.x;
    float hloc[CH], cA[CH];
    float a = 1.f, hv = 0.f;
    int s0 = t * CH;
    #pragma unroll
    for (int j = 0; j < CH; j++) {
        int r = b*Ss + s0 + j;
        float dt = g_dt[r*Hh + h];
        float dA = expf(dt * Ah);
        float u  = dt * g_xin[r*Hh + h] * g_p[(size_t)r*TOT + 2*DI + Hh + h*Nn + n];
        hv = dA * hv + u;
        a *= dA;
        hloc[j] = hv; cA[j] = a;
    }
    __shared__ float sA[256], sB[256];
    sA[t] = a; sB[t] = hv;
    __syncthreads();
    for (int off = 1; off < 256; off <<= 1) {
        float pa = 0.f, pb = 0.f;
        if (t >= off) { pa = sA[t - off]; pb = sB[t - off]; }
        __syncthreads();
        if (t >= off) { sB[t] = sA[t] * pb + sB[t]; sA[t] = sA[t] * pa; }
        __syncthreads();
    }
    float hin = (t == 0) ? 0.f : sB[t - 1];
    #pragma unroll
    for (int j = 0; j < CH; j++) {
        int r = b*Ss + s0 + j;
        g_hs[((size_t)r*Hh + h) * Nn + n] = hloc[j] + cA[j] * hin;
    }
}

// ---------------- y = sum_n h*C ----------------
__global__ void k_yred() {
    int i = blockIdx.x * blockDim.x + threadIdx.x;
    if (i >= ROWS * Hh) return;
    int h = i % Hh;
    int r = i / Hh;
    const float* hs = &g_hs[(size_t)i * Nn];
    const float* Cp = &g_p[(size_t)r*TOT + 2*DI + Hh + Hh*Nn + h*Nn];
    float s = 0.f;
    #pragma unroll
    for (int n = 0; n < Nn; n++) s += hs[n] * Cp[n];
    g_y[i] = s;
}

// ---------------- y_proj + gate fused with bf16 hi/lo split ----------------
__global__ void k_ymix_cvt(const float* __restrict__ yw) {
    int i = blockIdx.x * blockDim.x + threadIdx.x;
    if (i >= ROWS * DI) return;
    int c = i % DI;
    int r = i / DI;
    float4 w0 = ((const float4*)yw)[c*2];
    float4 w1 = ((const float4*)yw)[c*2 + 1];
    const float* y = &g_y[r*Hh];
    float s = y[0]*w0.x + y[1]*w0.y + y[2]*w0.z + y[3]*w0.w
            + y[4]*w1.x + y[5]*w1.y + y[6]*w1.z + y[7]*w1.w;
    float z = g_p[(size_t)r*TOT + c];
    float v = s * siluf(z);
    __nv_bfloat16 h, l;
    split_bf16(v, h, l);
    g_ahi[i] = h; g_alo[i] = l;
}

// ---------------- final layernorm fused with bf16 hi/lo split ----------------
__global__ void k_ln_cvt(const float* __restrict__ ln_w, const float* __restrict__ ln_b) {
    __shared__ float sh[256];
    int r = blockIdx.x, t = threadIdx.x;
    float v0 = g_x[(size_t)r*Dd + t];
    float v1 = g_x[(size_t)r*Dd + t + 256];
    float mu = blockReduceSum256(v0 + v1, sh) / (float)Dd;
    float d0 = v0 - mu, d1 = v1 - mu;
    float var = blockReduceSum256(d0*d0 + d1*d1, sh) / (float)Dd;
    float sc = rsqrtf(var + 1e-5f);
    float o0 = d0 * sc * ln_w[t]       + ln_b[t];
    float o1 = d1 * sc * ln_w[t + 256] + ln_b[t + 256];
    __nv_bfloat16 h, l;
    split_bf16(o0, h, l);
    g_ahi[(size_t)r*Dd + t] = h; g_alo[(size_t)r*Dd + t] = l;
    split_bf16(o1, h, l);
    g_ahi[(size_t)r*Dd + t + 256] = h; g_alo[(size_t)r*Dd + t + 256] = l;
}

// ---------------- launch ----------------
extern "C" void kernel_launch(void* const* d_in, const int* in_sizes, int n_in,
                              void* d_out, int out_size) {
    const int*   tok    = (const int*)  d_in[0];
    const float* emb    = (const float*)d_in[1];
    const float* rms_w  = (const float*)d_in[2];
    const float* in_w   = (const float*)d_in[3];
    const float* conv_w = (const float*)d_in[4];
    const float* dt_b   = (const float*)d_in[5];
    const float* A_log  = (const float*)d_in[6];
    const float* y_w    = (const float*)d_in[7];
    const float* out_w  = (const float*)d_in[8];
    const float* ln_w   = (const float*)d_in[9];
    const float* ln_b   = (const float*)d_in[10];
    const float* head_w = (const float*)d_in[11];
    const float* head_b = (const float*)d_in[12];
    float* out = (float*)d_out;

    float *p_x, *p_p;
    cudaGetSymbolAddress((void**)&p_x,  g_x);
    cudaGetSymbolAddress((void**)&p_p,  g_p);
    __nv_bfloat16 *p_ahi, *p_alo, *p_whi, *p_wlo;
    cudaGetSymbolAddress((void**)&p_ahi, g_ahi);
    cudaGetSymbolAddress((void**)&p_alo, g_alo);
    cudaGetSymbolAddress((void**)&p_whi, g_whi);
    cudaGetSymbolAddress((void**)&p_wlo, g_wlo);

    static int smem_set = 0;
    if (!smem_set) {
        cudaFuncSetAttribute(k_gemm_mma<0,0>, cudaFuncAttributeMaxDynamicSharedMemorySize, GEMM_SMEM);
        cudaFuncSetAttribute(k_gemm_mma<1,0>, cudaFuncAttributeMaxDynamicSharedMemorySize, GEMM_SMEM);
        cudaFuncSetAttribute(k_gemm_mma<0,1>, cudaFuncAttributeMaxDynamicSharedMemorySize, GEMM_SMEM);
        smem_set = 1;
    }

    k_embed<<<(ROWS*Dd + 255)/256, 256>>>(tok, emb);

    for (int L = 0; L < NLAYERS; L++) {
        k_rms_cvt<<<ROWS, 256>>>(rms_w + (size_t)L*Dd);
        k_cvt<<<(TOT*Dd/4 + 255)/256, 256>>>(in_w + (size_t)L*TOT*Dd, p_whi, p_wlo, TOT*Dd);

        // p = xn @ in_w^T  (M=4096, N=2312, K=512)
        {
            dim3 g((TOT + 127)/128, ROWS/128);
            k_gemm_mma<0,0><<<g, 256, GEMM_SMEM>>>(p_ahi, p_alo, p_whi, p_wlo,
                                                   nullptr, nullptr, p_p, TOT, Dd);
        }

        k_convdtx<<<ROWS, 256>>>(conv_w + (size_t)L*DI*Kk, dt_b + (size_t)L*Hh);
        k_scan<<<Bb*Hh*Nn, 256>>>(A_log + (size_t)L*Hh);
        k_yred<<<(ROWS*Hh + 255)/256, 256>>>();
        k_ymix_cvt<<<(ROWS*DI + 255)/256, 256>>>(y_w + (size_t)L*DI*Hh);

        // x = yi @ out_w^T + x  (M=4096, N=512, K=1024)
        k_cvt<<<(Dd*DI/4 + 255)/256, 256>>>(out_w + (size_t)L*Dd*DI, p_whi, p_wlo, Dd*DI);
        {
            dim3 g(Dd/128, ROWS/128);
            k_gemm_mma<1,0><<<g, 256, GEMM_SMEM>>>(p_ahi, p_alo, p_whi, p_wlo,
                                                   p_x, nullptr, p_x, Dd, DI);
        }
    }

    k_ln_cvt<<<ROWS, 256>>>(ln_w, ln_b);

    // out = xn @ head_w^T + head_b  (M=4096, N=32000, K=512)
    k_cvt<<<((int)((size_t)Vv*Dd/4) + 255)/256, 256>>>(head_w, p_whi, p_wlo, Vv*Dd);
    {
        dim3 g(Vv/128, ROWS/128);
        k_gemm_mma<0,1><<<g, 256, GEMM_SMEM>>>(p_ahi, p_alo, p_whi, p_wlo,
                                               nullptr, head_b, out, Vv, Dd);
    }
}

// round 9
// speedup vs baseline: 3.1149x; 1.1975x over previous
#include <cuda_runtime.h>
#include <cuda_bf16.h>
#include <math.h>
#include <stdint.h>

// ---------------- problem constants ----------------
#define Bb 2
#define Ss 2048
#define Dd 512
#define NLAYERS 6
#define DI 1024
#define Hh 8
#define Nn 16
#define Kk 4
#define Vv 32000
#define TOT (2*DI + Hh + 2*Hh*Nn)   // 2312
#define ROWS (Bb*Ss)                // 4096

// ---------------- scratch (static device globals; no allocation) ----------------
__device__ float g_x [ROWS*Dd];        // residual stream
__device__ float g_p [ROWS*TOT];       // in_proj output
__device__ float g_dt[ROWS*Hh];
__device__ float g_xin[ROWS*Hh];
__device__ float g_hs[ROWS*Hh*Nn];
__device__ float g_y [ROWS*Hh];
__device__ __align__(128) float g_act[ROWS*DI];   // fp32 GEMM A operand (xn / gated y)

// ---------------- small helpers ----------------
__device__ __forceinline__ float blockReduceSum256(float v, float* sh) {
    int t = threadIdx.x;
    sh[t] = v; __syncthreads();
    #pragma unroll
    for (int o = 128; o > 0; o >>= 1) {
        if (t < o) sh[t] += sh[t + o];
        __syncthreads();
    }
    float r = sh[0];
    __syncthreads();
    return r;
}
__device__ __forceinline__ float siluf(float v) { return v / (1.f + expf(-v)); }
__device__ __forceinline__ float softplusf(float v) {
    return (v > 0.f) ? (v + log1pf(expf(-v))) : log1pf(expf(v));
}

// ---------------- MMA primitives (arch-neutral, sm_80+) ----------------
__device__ __forceinline__ void cp16(uint32_t s, const void* g, uint32_t sz) {
    asm volatile("cp.async.cg.shared.global [%0], [%1], 16, %2;"
                 :: "r"(s), "l"(g), "r"(sz) : "memory");
}
__device__ __forceinline__ void cp_commit() {
    asm volatile("cp.async.commit_group;" ::: "memory");
}
__device__ __forceinline__ void cp_wait2() {
    asm volatile("cp.async.wait_group 2;" ::: "memory");
}
__device__ __forceinline__ void ldm4(uint32_t* r, uint32_t a) {
    asm volatile("ldmatrix.sync.aligned.m8n8.x4.shared.b16 {%0,%1,%2,%3}, [%4];"
                 : "=r"(r[0]), "=r"(r[1]), "=r"(r[2]), "=r"(r[3]) : "r"(a));
}
__device__ __forceinline__ void ldm2(uint32_t* r, uint32_t a) {
    asm volatile("ldmatrix.sync.aligned.m8n8.x2.shared.b16 {%0,%1}, [%2];"
                 : "=r"(r[0]), "=r"(r[1]) : "r"(a));
}
__device__ __forceinline__ uint32_t to_tf32(uint32_t bits) {
    uint32_t o;
    asm volatile("cvt.rna.tf32.f32 %0, %1;" : "=r"(o) : "f"(__uint_as_float(bits)));
    return o;
}
__device__ __forceinline__ void mma_tf32(float* d, const uint32_t* a,
                                         uint32_t b0, uint32_t b1) {
    asm volatile("mma.sync.aligned.m16n8k8.row.col.f32.tf32.tf32.f32 "
                 "{%0,%1,%2,%3}, {%4,%5,%6,%7}, {%8,%9}, {%0,%1,%2,%3};"
                 : "+f"(d[0]), "+f"(d[1]), "+f"(d[2]), "+f"(d[3])
                 : "r"(a[0]), "r"(a[1]), "r"(a[2]), "r"(a[3]), "r"(b0), "r"(b1));
}

// ---------------- TF32 GEMM: C[M,N] = A[M,K] @ B[N,K]^T (+res)(+bias) ----------------
// fp32 operands straight from global; single-pass tf32 MMA (cvt.rna in-register).
// CTA 128x128, BK=32, 3-stage cp.async pipeline, 8 warps (2x4), warp tile 64x32.
#define TSTRIDE 144                    // bytes per smem row (128 data + 16 pad)
#define TILE_F  (128*TSTRIDE)          // 18432
#define STAGE_F (2*TILE_F)             // A + B = 36864
#define GEMM_SMEM (3*STAGE_F)          // 110592

template<int ADD_RES, int ADD_BIAS>
__global__ void __launch_bounds__(256, 2)
k_gemm_tf32(const float* __restrict__ A, const float* __restrict__ B,
            const float* __restrict__ Res, const float* __restrict__ bias,
            float* __restrict__ C, int Nd, int Kd)
{
    extern __shared__ char smem[];
    const uint32_t sbase = (uint32_t)__cvta_generic_to_shared(smem);

    int tid = threadIdx.x, wid = tid >> 5, lane = tid & 31;
    int bm = blockIdx.y * 128, bn = blockIdx.x * 128;
    int wm = (wid >> 2) * 64, wn = (wid & 3) * 32;

    float acc[4][4][4];
    #pragma unroll
    for (int i = 0; i < 4; i++)
        #pragma unroll
        for (int j = 0; j < 4; j++)
            #pragma unroll
            for (int q = 0; q < 4; q++) acc[i][j][q] = 0.f;

    const int nch = Kd >> 5;

    auto load_stage = [&](int slot, int ch) {
        uint32_t sb = sbase + slot * STAGE_F;
        int k0 = ch << 5;
        #pragma unroll
        for (int j = 0; j < 4; j++) {
            int c = tid + j * 256;            // 0..1023
            int row = c >> 3, q = c & 7;
            uint32_t so = (uint32_t)(row * TSTRIDE + q * 16);
            size_t ga = (size_t)(bm + row) * Kd + k0 + q * 4;
            cp16(sb + so, A + ga, 16);
            int brow = bn + row;
            uint32_t sz = (brow < Nd) ? 16u : 0u;
            int brc = brow < Nd ? brow : (Nd - 1);
            size_t gb = (size_t)brc * Kd + k0 + q * 4;
            cp16(sb + TILE_F + so, B + gb, sz);
        }
        cp_commit();
    };

    load_stage(0, 0);
    if (nch > 1) load_stage(1, 1); else cp_commit();

    for (int ch = 0; ch < nch; ch++) {
        if (ch + 2 < nch) load_stage((ch + 2) % 3, ch + 2);
        else              cp_commit();
        cp_wait2();
        __syncthreads();

        uint32_t sb = sbase + (ch % 3) * STAGE_F;
        uint32_t sA = sb, sB = sb + TILE_F;

        #pragma unroll
        for (int k8 = 0; k8 < 4; k8++) {
            // B fragments: 4 n8 tiles, ldmatrix.x2 each
            uint32_t bF[4][2];
            {
                int brow = lane & 7;
                int bcol = (lane & 8) ? 16 : 0;
                #pragma unroll
                for (int nt = 0; nt < 4; nt++) {
                    uint32_t bo = (uint32_t)((wn + nt*8 + brow) * TSTRIDE + k8 * 32 + bcol);
                    ldm2(bF[nt], sB + bo);
                    bF[nt][0] = to_tf32(bF[nt][0]);
                    bF[nt][1] = to_tf32(bF[nt][1]);
                }
            }
            // A fragments streamed per 16-row subtile
            int arow = (lane & 7) + ((lane & 8) ? 8 : 0);
            int acol = (lane & 16) ? 16 : 0;
            #pragma unroll
            for (int mt = 0; mt < 4; mt++) {
                uint32_t aF[4];
                uint32_t ao = (uint32_t)((wm + mt*16 + arow) * TSTRIDE + k8 * 32 + acol);
                ldm4(aF, sA + ao);
                #pragma unroll
                for (int q = 0; q < 4; q++) aF[q] = to_tf32(aF[q]);
                #pragma unroll
                for (int nt = 0; nt < 4; nt++)
                    mma_tf32(acc[mt][nt], aF, bF[nt][0], bF[nt][1]);
            }
        }
        __syncthreads();
    }

    #pragma unroll
    for (int mt = 0; mt < 4; mt++) {
        int r0 = bm + wm + mt*16 + (lane >> 2);
        #pragma unroll
        for (int nt = 0; nt < 4; nt++) {
            int n = bn + wn + nt*8 + (lane & 3) * 2;
            if (n < Nd) {
                float2 v0 = make_float2(acc[mt][nt][0], acc[mt][nt][1]);
                float2 v1 = make_float2(acc[mt][nt][2], acc[mt][nt][3]);
                if (ADD_BIAS) {
                    float2 bv = *(const float2*)(bias + n);
                    v0.x += bv.x; v0.y += bv.y; v1.x += bv.x; v1.y += bv.y;
                }
                if (ADD_RES) {
                    float2 r0v = *(const float2*)(Res + (size_t)r0 * Nd + n);
                    float2 r1v = *(const float2*)(Res + (size_t)(r0+8) * Nd + n);
                    v0.x += r0v.x; v0.y += r0v.y; v1.x += r1v.x; v1.y += r1v.y;
                }
                *(float2*)(C + (size_t)r0 * Nd + n)     = v0;
                *(float2*)(C + (size_t)(r0+8) * Nd + n) = v1;
            }
        }
    }
}

// ---------------- embedding gather ----------------
__global__ void k_embed(const int* __restrict__ tok, const float* __restrict__ emb) {
    int i = blockIdx.x * blockDim.x + threadIdx.x;
    if (i < ROWS * Dd) {
        int r = i / Dd, d = i - r * Dd;
        g_x[i] = emb[(size_t)tok[r] * Dd + d];
    }
}

// ---------------- rmsnorm -> g_act (fp32) ----------------
__global__ void k_rms(const float* __restrict__ rms_w) {
    __shared__ float sh[256];
    int r = blockIdx.x, t = threadIdx.x;
    float v0 = g_x[(size_t)r*Dd + t];
    float v1 = g_x[(size_t)r*Dd + t + 256];
    float ss = blockReduceSum256(v0*v0 + v1*v1, sh);
    float sc = rsqrtf(ss / (float)Dd + 1e-6f);
    g_act[(size_t)r*Dd + t]       = v0 * sc * rms_w[t];
    g_act[(size_t)r*Dd + t + 256] = v1 * sc * rms_w[t + 256];
}

// ---------------- fused conv+SiLU+head-mean+dt-softplus ----------------
__global__ __launch_bounds__(256)
void k_convdtx(const float* __restrict__ cw, const float* __restrict__ dtb) {
    int r = blockIdx.x;
    int s = r % Ss, b = r / Ss;
    int w = threadIdx.x >> 5, lane = threadIdx.x & 31;
    float sum = 0.f;
    #pragma unroll
    for (int j = 0; j < 4; j++) {
        int c = w * 128 + lane + 32 * j;
        float4 cv = ((const float4*)cw)[c];
        float acc = 0.f;
        const float* base = &g_p[(size_t)(b*Ss) * TOT + DI + c];
        if (s >= 3) {
            acc = base[(size_t)(s-3)*TOT] * cv.x + base[(size_t)(s-2)*TOT] * cv.y
                + base[(size_t)(s-1)*TOT] * cv.z + base[(size_t)s*TOT] * cv.w;
        } else {
            #pragma unroll
            for (int k = 0; k < 4; k++) {
                int sp = s + k - 3;
                if (sp >= 0) acc += base[(size_t)sp*TOT] * ((const float*)&cv)[k];
            }
        }
        sum += siluf(acc);
    }
    #pragma unroll
    for (int o = 16; o > 0; o >>= 1) sum += __shfl_xor_sync(0xffffffffu, sum, o);
    if (lane == 0) {
        g_xin[r*Hh + w] = sum * (1.f / 128.f);
        float dt = g_p[(size_t)r*TOT + 2*DI + w] + dtb[w];
        g_dt[r*Hh + w] = softplusf(dt);
    }
}

// ---------------- parallel associative scan ----------------
__global__ __launch_bounds__(256)
void k_scan(const float* __restrict__ A_log) {
    const int CH = Ss / 256;
    int chain = blockIdx.x;
    int n = chain % Nn;
    int h = (chain / Nn) % Hh;
    int b = chain / (Nn * Hh);
    float Ah = -expf(A_log[h]);

    int t = threadIdx.x;
    float hloc[CH], cA[CH];
    float a = 1.f, hv = 0.f;
    int s0 = t * CH;
    #pragma unroll
    for (int j = 0; j < CH; j++) {
        int r = b*Ss + s0 + j;
        float dt = g_dt[r*Hh + h];
        float dA = expf(dt * Ah);
        float u  = dt * g_xin[r*Hh + h] * g_p[(size_t)r*TOT + 2*DI + Hh + h*Nn + n];
        hv = dA * hv + u;
        a *= dA;
        hloc[j] = hv; cA[j] = a;
    }
    __shared__ float sA[256], sB[256];
    sA[t] = a; sB[t] = hv;
    __syncthreads();
    for (int off = 1; off < 256; off <<= 1) {
        float pa = 0.f, pb = 0.f;
        if (t >= off) { pa = sA[t - off]; pb = sB[t - off]; }
        __syncthreads();
        if (t >= off) { sB[t] = sA[t] * pb + sB[t]; sA[t] = sA[t] * pa; }
        __syncthreads();
    }
    float hin = (t == 0) ? 0.f : sB[t - 1];
    #pragma unroll
    for (int j = 0; j < CH; j++) {
        int r = b*Ss + s0 + j;
        g_hs[((size_t)r*Hh + h) * Nn + n] = hloc[j] + cA[j] * hin;
    }
}

// ---------------- y = sum_n h*C ----------------
__global__ void k_yred() {
    int i = blockIdx.x * blockDim.x + threadIdx.x;
    if (i >= ROWS * Hh) return;
    int h = i % Hh;
    int r = i / Hh;
    const float* hs = &g_hs[(size_t)i * Nn];
    const float* Cp = &g_p[(size_t)r*TOT + 2*DI + Hh + Hh*Nn + h*Nn];
    float s = 0.f;
    #pragma unroll
    for (int n = 0; n < Nn; n++) s += hs[n] * Cp[n];
    g_y[i] = s;
}

// ---------------- y_proj + gate -> g_act (fp32) ----------------
__global__ void k_ymix(const float* __restrict__ yw) {
    int i = blockIdx.x * blockDim.x + threadIdx.x;
    if (i >= ROWS * DI) return;
    int c = i % DI;
    int r = i / DI;
    float4 w0 = ((const float4*)yw)[c*2];
    float4 w1 = ((const float4*)yw)[c*2 + 1];
    const float* y = &g_y[r*Hh];
    float s = y[0]*w0.x + y[1]*w0.y + y[2]*w0.z + y[3]*w0.w
            + y[4]*w1.x + y[5]*w1.y + y[6]*w1.z + y[7]*w1.w;
    float z = g_p[(size_t)r*TOT + c];
    g_act[i] = s * siluf(z);
}

// ---------------- final layernorm -> g_act ----------------
__global__ void k_ln(const float* __restrict__ ln_w, const float* __restrict__ ln_b) {
    __shared__ float sh[256];
    int r = blockIdx.x, t = threadIdx.x;
    float v0 = g_x[(size_t)r*Dd + t];
    float v1 = g_x[(size_t)r*Dd + t + 256];
    float mu = blockReduceSum256(v0 + v1, sh) / (float)Dd;
    float d0 = v0 - mu, d1 = v1 - mu;
    float var = blockReduceSum256(d0*d0 + d1*d1, sh) / (float)Dd;
    float sc = rsqrtf(var + 1e-5f);
    g_act[(size_t)r*Dd + t]       = d0 * sc * ln_w[t]       + ln_b[t];
    g_act[(size_t)r*Dd + t + 256] = d1 * sc * ln_w[t + 256] + ln_b[t + 256];
}

// ---------------- launch ----------------
extern "C" void kernel_launch(void* const* d_in, const int* in_sizes, int n_in,
                              void* d_out, int out_size) {
    const int*   tok    = (const int*)  d_in[0];
    const float* emb    = (const float*)d_in[1];
    const float* rms_w  = (const float*)d_in[2];
    const float* in_w   = (const float*)d_in[3];
    const float* conv_w = (const float*)d_in[4];
    const float* dt_b   = (const float*)d_in[5];
    const float* A_log  = (const float*)d_in[6];
    const float* y_w    = (const float*)d_in[7];
    const float* out_w  = (const float*)d_in[8];
    const float* ln_w   = (const float*)d_in[9];
    const float* ln_b   = (const float*)d_in[10];
    const float* head_w = (const float*)d_in[11];
    const float* head_b = (const float*)d_in[12];
    float* out = (float*)d_out;

    float *p_x, *p_p, *p_act;
    cudaGetSymbolAddress((void**)&p_x,   g_x);
    cudaGetSymbolAddress((void**)&p_p,   g_p);
    cudaGetSymbolAddress((void**)&p_act, g_act);

    static int smem_set = 0;
    if (!smem_set) {
        cudaFuncSetAttribute(k_gemm_tf32<0,0>, cudaFuncAttributeMaxDynamicSharedMemorySize, GEMM_SMEM);
        cudaFuncSetAttribute(k_gemm_tf32<1,0>, cudaFuncAttributeMaxDynamicSharedMemorySize, GEMM_SMEM);
        cudaFuncSetAttribute(k_gemm_tf32<0,1>, cudaFuncAttributeMaxDynamicSharedMemorySize, GEMM_SMEM);
        smem_set = 1;
    }

    k_embed<<<(ROWS*Dd + 255)/256, 256>>>(tok, emb);

    for (int L = 0; L < NLAYERS; L++) {
        k_rms<<<ROWS, 256>>>(rms_w + (size_t)L*Dd);

        // p = xn @ in_w^T  (M=4096, N=2312, K=512)
        {
            dim3 g((TOT + 127)/128, ROWS/128);
            k_gemm_tf32<0,0><<<g, 256, GEMM_SMEM>>>(p_act, in_w + (size_t)L*TOT*Dd,
                                                    nullptr, nullptr, p_p, TOT, Dd);
        }

        k_convdtx<<<ROWS, 256>>>(conv_w + (size_t)L*DI*Kk, dt_b + (size_t)L*Hh);
        k_scan<<<Bb*Hh*Nn, 256>>>(A_log + (size_t)L*Hh);
        k_yred<<<(ROWS*Hh + 255)/256, 256>>>();
        k_ymix<<<(ROWS*DI + 255)/256, 256>>>(y_w + (size_t)L*DI*Hh);

        // x = yi @ out_w^T + x  (M=4096, N=512, K=1024)
        {
            dim3 g(Dd/128, ROWS/128);
            k_gemm_tf32<1,0><<<g, 256, GEMM_SMEM>>>(p_act, out_w + (size_t)L*Dd*DI,
                                                    p_x, nullptr, p_x, Dd, DI);
        }
    }

    k_ln<<<ROWS, 256>>>(ln_w, ln_b);

    // out = xn @ head_w^T + head_b  (M=4096, N=32000, K=512)
    {
        dim3 g(Vv/128, ROWS/128);
        k_gemm_tf32<0,1><<<g, 256, GEMM_SMEM>>>(p_act, head_w,
                                                nullptr, head_b, out, Vv, Dd);
    }
}

// round 12
// speedup vs baseline: 4.7066x; 1.5110x over previous
#include <cuda_runtime.h>
#include <cuda_fp16.h>
#include <math.h>
#include <stdint.h>

// ---------------- problem constants ----------------
#define Bb 2
#define Ss 2048
#define Dd 512
#define NLAYERS 6
#define DI 1024
#define Hh 8
#define Nn 16
#define Kk 4
#define Vv 32000
#define TOT (2*DI + Hh + 2*Hh*Nn)   // 2312
#define ROWS (Bb*Ss)                // 4096

// ---------------- scratch (static device globals; no allocation) ----------------
__device__ float g_x [ROWS*Dd];        // residual stream
__device__ float g_p [ROWS*TOT];       // in_proj output
__device__ float g_dt[ROWS*Hh];
__device__ float g_xin[ROWS*Hh];
__device__ float g_hs[ROWS*Hh*Nn];
__device__ float g_y [ROWS*Hh];
__device__ __align__(128) __half g_af16[ROWS*DI];        // fp16 A operand
__device__ __align__(128) __half g_wf16[(size_t)Vv*Dd];  // fp16 B operand (weights)

// ---------------- small helpers ----------------
__device__ __forceinline__ float blockReduceSum256(float v, float* sh) {
    int t = threadIdx.x;
    sh[t] = v; __syncthreads();
    #pragma unroll
    for (int o = 128; o > 0; o >>= 1) {
        if (t < o) sh[t] += sh[t + o];
        __syncthreads();
    }
    float r = sh[0];
    __syncthreads();
    return r;
}
__device__ __forceinline__ float siluf(float v) { return v / (1.f + expf(-v)); }
__device__ __forceinline__ float softplusf(float v) {
    return (v > 0.f) ? (v + log1pf(expf(-v))) : log1pf(expf(v));
}

// ---------------- MMA primitives (arch-neutral, sm_80+) ----------------
__device__ __forceinline__ void cp16(uint32_t s, const void* g, uint32_t sz) {
    asm volatile("cp.async.cg.shared.global [%0], [%1], 16, %2;"
                 :: "r"(s), "l"(g), "r"(sz) : "memory");
}
__device__ __forceinline__ void cp_commit() {
    asm volatile("cp.async.commit_group;" ::: "memory");
}
__device__ __forceinline__ void cp_wait2() {
    asm volatile("cp.async.wait_group 2;" ::: "memory");
}
__device__ __forceinline__ void ldm4(uint32_t* r, uint32_t a) {
    asm volatile("ldmatrix.sync.aligned.m8n8.x4.shared.b16 {%0,%1,%2,%3}, [%4];"
                 : "=r"(r[0]), "=r"(r[1]), "=r"(r[2]), "=r"(r[3]) : "r"(a));
}
__device__ __forceinline__ void mma16816(float* d, const uint32_t* a,
                                         uint32_t b0, uint32_t b1) {
    asm volatile("mma.sync.aligned.m16n8k16.row.col.f32.f16.f16.f32 "
                 "{%0,%1,%2,%3}, {%4,%5,%6,%7}, {%8,%9}, {%0,%1,%2,%3};"
                 : "+f"(d[0]), "+f"(d[1]), "+f"(d[2]), "+f"(d[3])
                 : "r"(a[0]), "r"(a[1]), "r"(a[2]), "r"(a[3]), "r"(b0), "r"(b1));
}

// ---------------- fp32 -> fp16 weight convert ----------------
__global__ void k_wcvt(const float* __restrict__ src, __half* __restrict__ dst, int n) {
    int i = (blockIdx.x * blockDim.x + threadIdx.x) * 4;
    if (i >= n) return;
    float4 v = *(const float4*)(src + i);
    __half2 h0 = __floats2half2_rn(v.x, v.y);
    __half2 h1 = __floats2half2_rn(v.z, v.w);
    ((__half2*)(dst + i))[0] = h0;
    ((__half2*)(dst + i))[1] = h1;
}

// ---------------- FP16 GEMM: C[M,N] = A[M,K] @ B[N,K]^T (+res)(+bias) ----------------
// single-pass fp16, fp32 accum. CTA 128x128, BK=32, 4-stage cp.async pipeline,
// 8 warps (2x4), warp tile 64x32. HSTRIDE must be a multiple of 16 for cp.async.
#define HSTRIDE 80                     // bytes per smem row (64 data + 16 pad)
#define TILE_H  (128*HSTRIDE)          // 10240
#define STAGE_H (2*TILE_H)             // A + B = 20480
#define NSTAGE  4
#define GEMM_SMEM (NSTAGE*STAGE_H)     // 81920

template<int ADD_RES, int ADD_BIAS>
__global__ void __launch_bounds__(256, 2)
k_gemm_fp16(const __half* __restrict__ A, const __half* __restrict__ B,
            const float* __restrict__ Res, const float* __restrict__ bias,
            float* __restrict__ C, int Nd, int Kd)
{
    extern __shared__ char smem[];
    const uint32_t sbase = (uint32_t)__cvta_generic_to_shared(smem);

    int tid = threadIdx.x, wid = tid >> 5, lane = tid & 31;
    int bm = blockIdx.y * 128, bn = blockIdx.x * 128;
    int wm = (wid >> 2) * 64, wn = (wid & 3) * 32;

    float acc[4][4][4];
    #pragma unroll
    for (int i = 0; i < 4; i++)
        #pragma unroll
        for (int j = 0; j < 4; j++)
            #pragma unroll
            for (int q = 0; q < 4; q++) acc[i][j][q] = 0.f;

    const int nch = Kd >> 5;

    // stage loader: A and B tiles, 128 rows x 64B each -> 2 cp16/thread/tile
    auto load_stage = [&](int slot, int ch) {
        uint32_t sb = sbase + slot * STAGE_H;
        int k0 = ch << 5;
        #pragma unroll
        for (int j = 0; j < 2; j++) {
            int c = tid + j * 256;            // 0..511
            int row = c >> 2, q = c & 3;
            uint32_t so = (uint32_t)(row * HSTRIDE + q * 16);
            size_t ga = (size_t)(bm + row) * Kd + k0 + q * 8;
            cp16(sb + so, A + ga, 16);
            int brow = bn + row;
            uint32_t sz = (brow < Nd) ? 16u : 0u;
            int brc = brow < Nd ? brow : (Nd - 1);
            size_t gb = (size_t)brc * Kd + k0 + q * 8;
            cp16(sb + TILE_H + so, B + gb, sz);
        }
        cp_commit();
    };

    load_stage(0, 0);
    if (nch > 1) load_stage(1, 1); else cp_commit();
    if (nch > 2) load_stage(2, 2); else cp_commit();

    for (int ch = 0; ch < nch; ch++) {
        if (ch + 3 < nch) load_stage((ch + 3) & 3, ch + 3);
        else              cp_commit();
        cp_wait2();
        __syncthreads();

        uint32_t sb = sbase + (ch & 3) * STAGE_H;
        uint32_t sA = sb, sB = sb + TILE_H;

        #pragma unroll
        for (int ks = 0; ks < 2; ks++) {
            // B fragments for both n16 subtiles (held across mt loop)
            uint32_t bF[2][4];
            int brow = ((lane & 16) ? 8 : 0) + (lane & 7);
            int bcb  = ks * 32 + ((lane & 8) ? 16 : 0);
            #pragma unroll
            for (int ntp = 0; ntp < 2; ntp++) {
                uint32_t bo = (uint32_t)((wn + ntp*16 + brow) * HSTRIDE + bcb);
                ldm4(bF[ntp], sB + bo);
            }
            // stream A fragments per 16-row subtile
            int arow = (lane & 15);
            int acb  = ks * 32 + ((lane & 16) ? 16 : 0);
            #pragma unroll
            for (int mt = 0; mt < 4; mt++) {
                uint32_t aF[4];
                uint32_t ao = (uint32_t)((wm + mt*16 + arow) * HSTRIDE + acb);
                ldm4(aF, sA + ao);
                #pragma unroll
                for (int ntp = 0; ntp < 2; ntp++) {
                    int nt0 = ntp * 2;
                    mma16816(acc[mt][nt0],   aF, bF[ntp][0], bF[ntp][1]);
                    mma16816(acc[mt][nt0+1], aF, bF[ntp][2], bF[ntp][3]);
                }
            }
        }
        __syncthreads();
    }

    #pragma unroll
    for (int mt = 0; mt < 4; mt++) {
        int r0 = bm + wm + mt*16 + (lane >> 2);
        #pragma unroll
        for (int nt = 0; nt < 4; nt++) {
            int n = bn + wn + nt*8 + (lane & 3) * 2;
            if (n < Nd) {
                float2 v0 = make_float2(acc[mt][nt][0], acc[mt][nt][1]);
                float2 v1 = make_float2(acc[mt][nt][2], acc[mt][nt][3]);
                if (ADD_BIAS) {
                    float2 bv = *(const float2*)(bias + n);
                    v0.x += bv.x; v0.y += bv.y; v1.x += bv.x; v1.y += bv.y;
                }
                if (ADD_RES) {
                    float2 r0v = *(const float2*)(Res + (size_t)r0 * Nd + n);
                    float2 r1v = *(const float2*)(Res + (size_t)(r0+8) * Nd + n);
                    v0.x += r0v.x; v0.y += r0v.y; v1.x += r1v.x; v1.y += r1v.y;
                }
                *(float2*)(C + (size_t)r0 * Nd + n)     = v0;
                *(float2*)(C + (size_t)(r0+8) * Nd + n) = v1;
            }
        }
    }
}

// ---------------- embedding gather ----------------
__global__ void k_embed(const int* __restrict__ tok, const float* __restrict__ emb) {
    int i = blockIdx.x * blockDim.x + threadIdx.x;
    if (i < ROWS * Dd) {
        int r = i / Dd, d = i - r * Dd;
        g_x[i] = emb[(size_t)tok[r] * Dd + d];
    }
}

// ---------------- rmsnorm -> fp16 A operand ----------------
__global__ void k_rms(const float* __restrict__ rms_w) {
    __shared__ float sh[256];
    int r = blockIdx.x, t = threadIdx.x;
    float v0 = g_x[(size_t)r*Dd + t];
    float v1 = g_x[(size_t)r*Dd + t + 256];
    float ss = blockReduceSum256(v0*v0 + v1*v1, sh);
    float sc = rsqrtf(ss / (float)Dd + 1e-6f);
    g_af16[(size_t)r*Dd + t]       = __float2half_rn(v0 * sc * rms_w[t]);
    g_af16[(size_t)r*Dd + t + 256] = __float2half_rn(v1 * sc * rms_w[t + 256]);
}

// ---------------- fused conv+SiLU+head-mean+dt-softplus ----------------
__global__ __launch_bounds__(256)
void k_convdtx(const float* __restrict__ cw, const float* __restrict__ dtb) {
    int r = blockIdx.x;
    int s = r % Ss, b = r / Ss;
    int w = threadIdx.x >> 5, lane = threadIdx.x & 31;
    float sum = 0.f;
    #pragma unroll
    for (int j = 0; j < 4; j++) {
        int c = w * 128 + lane + 32 * j;
        float4 cv = ((const float4*)cw)[c];
        float acc = 0.f;
        const float* base = &g_p[(size_t)(b*Ss) * TOT + DI + c];
        if (s >= 3) {
            acc = base[(size_t)(s-3)*TOT] * cv.x + base[(size_t)(s-2)*TOT] * cv.y
                + base[(size_t)(s-1)*TOT] * cv.z + base[(size_t)s*TOT] * cv.w;
        } else {
            #pragma unroll
            for (int k = 0; k < 4; k++) {
                int sp = s + k - 3;
                if (sp >= 0) acc += base[(size_t)sp*TOT] * ((const float*)&cv)[k];
            }
        }
        sum += siluf(acc);
    }
    #pragma unroll
    for (int o = 16; o > 0; o >>= 1) sum += __shfl_xor_sync(0xffffffffu, sum, o);
    if (lane == 0) {
        g_xin[r*Hh + w] = sum * (1.f / 128.f);
        float dt = g_p[(size_t)r*TOT + 2*DI + w] + dtb[w];
        g_dt[r*Hh + w] = softplusf(dt);
    }
}

// ---------------- parallel associative scan ----------------
__global__ __launch_bounds__(256)
void k_scan(const float* __restrict__ A_log) {
    const int CH = Ss / 256;
    int chain = blockIdx.x;
    int n = chain % Nn;
    int h = (chain / Nn) % Hh;
    int b = chain / (Nn * Hh);
    float Ah = -expf(A_log[h]);

    int t = threadIdx.x;
    float hloc[CH], cA[CH];
    float a = 1.f, hv = 0.f;
    int s0 = t * CH;
    #pragma unroll
    for (int j = 0; j < CH; j++) {
        int r = b*Ss + s0 + j;
        float dt = g_dt[r*Hh + h];
        float dA = expf(dt * Ah);
        float u  = dt * g_xin[r*Hh + h] * g_p[(size_t)r*TOT + 2*DI + Hh + h*Nn + n];
        hv = dA * hv + u;
        a *= dA;
        hloc[j] = hv; cA[j] = a;
    }
    __shared__ float sA[256], sB[256];
    sA[t] = a; sB[t] = hv;
    __syncthreads();
    for (int off = 1; off < 256; off <<= 1) {
        float pa = 0.f, pb = 0.f;
        if (t >= off) { pa = sA[t - off]; pb = sB[t - off]; }
        __syncthreads();
        if (t >= off) { sB[t] = sA[t] * pb + sB[t]; sA[t] = sA[t] * pa; }
        __syncthreads();
    }
    float hin = (t == 0) ? 0.f : sB[t - 1];
    #pragma unroll
    for (int j = 0; j < CH; j++) {
        int r = b*Ss + s0 + j;
        g_hs[((size_t)r*Hh + h) * Nn + n] = hloc[j] + cA[j] * hin;
    }
}

// ---------------- y = sum_n h*C ----------------
__global__ void k_yred() {
    int i = blockIdx.x * blockDim.x + threadIdx.x;
    if (i >= ROWS * Hh) return;
    int h = i % Hh;
    int r = i / Hh;
    const float* hs = &g_hs[(size_t)i * Nn];
    const float* Cp = &g_p[(size_t)r*TOT + 2*DI + Hh + Hh*Nn + h*Nn];
    float s = 0.f;
    #pragma unroll
    for (int n = 0; n < Nn; n++) s += hs[n] * Cp[n];
    g_y[i] = s;
}

// ---------------- y_proj + gate -> fp16 A operand ----------------
__global__ void k_ymix(const float* __restrict__ yw) {
    int i = blockIdx.x * blockDim.x + threadIdx.x;
    if (i >= ROWS * DI) return;
    int c = i % DI;
    int r = i / DI;
    float4 w0 = ((const float4*)yw)[c*2];
    float4 w1 = ((const float4*)yw)[c*2 + 1];
    const float* y = &g_y[r*Hh];
    float s = y[0]*w0.x + y[1]*w0.y + y[2]*w0.z + y[3]*w0.w
            + y[4]*w1.x + y[5]*w1.y + y[6]*w1.z + y[7]*w1.w;
    float z = g_p[(size_t)r*TOT + c];
    g_af16[i] = __float2half_rn(s * siluf(z));
}

// ---------------- final layernorm -> fp16 A operand ----------------
__global__ void k_ln(const float* __restrict__ ln_w, const float* __restrict__ ln_b) {
    __shared__ float sh[256];
    int r = blockIdx.x, t = threadIdx.x;
    float v0 = g_x[(size_t)r*Dd + t];
    float v1 = g_x[(size_t)r*Dd + t + 256];
    float mu = blockReduceSum256(v0 + v1, sh) / (float)Dd;
    float d0 = v0 - mu, d1 = v1 - mu;
    float var = blockReduceSum256(d0*d0 + d1*d1, sh) / (float)Dd;
    float sc = rsqrtf(var + 1e-5f);
    g_af16[(size_t)r*Dd + t]       = __float2half_rn(d0 * sc * ln_w[t]       + ln_b[t]);
    g_af16[(size_t)r*Dd + t + 256] = __float2half_rn(d1 * sc * ln_w[t + 256] + ln_b[t + 256]);
}

// ---------------- launch ----------------
extern "C" void kernel_launch(void* const* d_in, const int* in_sizes, int n_in,
                              void* d_out, int out_size) {
    const int*   tok    = (const int*)  d_in[0];
    const float* emb    = (const float*)d_in[1];
    const float* rms_w  = (const float*)d_in[2];
    const float* in_w   = (const float*)d_in[3];
    const float* conv_w = (const float*)d_in[4];
    const float* dt_b   = (const float*)d_in[5];
    const float* A_log  = (const float*)d_in[6];
    const float* y_w    = (const float*)d_in[7];
    const float* out_w  = (const float*)d_in[8];
    const float* ln_w   = (const float*)d_in[9];
    const float* ln_b   = (const float*)d_in[10];
    const float* head_w = (const float*)d_in[11];
    const float* head_b = (const float*)d_in[12];
    float* out = (float*)d_out;

    float *p_x, *p_p;
    cudaGetSymbolAddress((void**)&p_x, g_x);
    cudaGetSymbolAddress((void**)&p_p, g_p);
    __half *p_a, *p_w;
    cudaGetSymbolAddress((void**)&p_a, g_af16);
    cudaGetSymbolAddress((void**)&p_w, g_wf16);

    static int smem_set = 0;
    if (!smem_set) {
        cudaFuncSetAttribute(k_gemm_fp16<0,0>, cudaFuncAttributeMaxDynamicSharedMemorySize, GEMM_SMEM);
        cudaFuncSetAttribute(k_gemm_fp16<1,0>, cudaFuncAttributeMaxDynamicSharedMemorySize, GEMM_SMEM);
        cudaFuncSetAttribute(k_gemm_fp16<0,1>, cudaFuncAttributeMaxDynamicSharedMemorySize, GEMM_SMEM);
        smem_set = 1;
    }

    k_embed<<<(ROWS*Dd + 255)/256, 256>>>(tok, emb);

    for (int L = 0; L < NLAYERS; L++) {
        k_rms<<<ROWS, 256>>>(rms_w + (size_t)L*Dd);
        k_wcvt<<<(TOT*Dd/4 + 255)/256, 256>>>(in_w + (size_t)L*TOT*Dd, p_w, TOT*Dd);

        // p = xn @ in_w^T  (M=4096, N=2312, K=512)
        {
            dim3 g((TOT + 127)/128, ROWS/128);
            k_gemm_fp16<0,0><<<g, 256, GEMM_SMEM>>>(p_a, p_w, nullptr, nullptr,
                                                    p_p, TOT, Dd);
        }

        k_convdtx<<<ROWS, 256>>>(conv_w + (size_t)L*DI*Kk, dt_b + (size_t)L*Hh);
        k_scan<<<Bb*Hh*Nn, 256>>>(A_log + (size_t)L*Hh);
        k_yred<<<(ROWS*Hh + 255)/256, 256>>>();
        k_ymix<<<(ROWS*DI + 255)/256, 256>>>(y_w + (size_t)L*DI*Hh);

        // x = yi @ out_w^T + x  (M=4096, N=512, K=1024)
        k_wcvt<<<(Dd*DI/4 + 255)/256, 256>>>(out_w + (size_t)L*Dd*DI, p_w, Dd*DI);
        {
            dim3 g(Dd/128, ROWS/128);
            k_gemm_fp16<1,0><<<g, 256, GEMM_SMEM>>>(p_a, p_w, p_x, nullptr,
                                                    p_x, Dd, DI);
        }
    }

    k_ln<<<ROWS, 256>>>(ln_w, ln_b);

    // out = xn @ head_w^T + head_b  (M=4096, N=32000, K=512)
    k_wcvt<<<((int)((size_t)Vv*Dd/4) + 255)/256, 256>>>(head_w, p_w, Vv*Dd);
    {
        dim3 g(Vv/128, ROWS/128);
        k_gemm_fp16<0,1><<<g, 256, GEMM_SMEM>>>(p_a, p_w, nullptr, head_b,
                                                out, Vv, Dd);
    }
}

// round 13
// speedup vs baseline: 5.2688x; 1.1195x over previous
#include <cuda_runtime.h>
#include <cuda_fp16.h>
#include <math.h>
#include <stdint.h>

// ---------------- problem constants ----------------
#define Bb 2
#define Ss 2048
#define Dd 512
#define NLAYERS 6
#define DI 1024
#define Hh 8
#define Nn 16
#define Kk 4
#define Vv 32000
#define TOT (2*DI + Hh + 2*Hh*Nn)   // 2312
#define ROWS (Bb*Ss)                // 4096

// weight pool offsets (halves)
#define WOFF_IN   0
#define WOFF_OUT  (NLAYERS*TOT*Dd)                    // 7102464
#define WOFF_HEAD (WOFF_OUT + NLAYERS*Dd*DI)          // 10248192
#define WPOOL     (WOFF_HEAD + (size_t)Vv*Dd)         // 26632192

// ---------------- scratch (static device globals; no allocation) ----------------
__device__ float g_x [ROWS*Dd];        // residual stream
__device__ float g_p [ROWS*TOT];       // in_proj output
__device__ float g_dt[ROWS*Hh];
__device__ float g_xin[ROWS*Hh];
__device__ float g_hs[ROWS*Hh*Nn];
__device__ float g_y [ROWS*Hh];
__device__ __align__(128) __half g_af16[ROWS*DI];     // fp16 A operand
__device__ __align__(128) __half g_wf16[WPOOL];       // fp16 weights (all tensors)

// ---------------- small helpers ----------------
__device__ __forceinline__ float blockReduceSum256(float v, float* sh) {
    int t = threadIdx.x;
    sh[t] = v; __syncthreads();
    #pragma unroll
    for (int o = 128; o > 0; o >>= 1) {
        if (t < o) sh[t] += sh[t + o];
        __syncthreads();
    }
    float r = sh[0];
    __syncthreads();
    return r;
}
__device__ __forceinline__ float siluf(float v) { return v / (1.f + expf(-v)); }
__device__ __forceinline__ float softplusf(float v) {
    return (v > 0.f) ? (v + log1pf(expf(-v))) : log1pf(expf(v));
}

// ---------------- MMA primitives (arch-neutral, sm_80+) ----------------
__device__ __forceinline__ void cp16(uint32_t s, const void* g, uint32_t sz) {
    asm volatile("cp.async.cg.shared.global [%0], [%1], 16, %2;"
                 :: "r"(s), "l"(g), "r"(sz) : "memory");
}
__device__ __forceinline__ void cp_commit() {
    asm volatile("cp.async.commit_group;" ::: "memory");
}
__device__ __forceinline__ void cp_wait1() {
    asm volatile("cp.async.wait_group 1;" ::: "memory");
}
__device__ __forceinline__ void ldm4(uint32_t* r, uint32_t a) {
    asm volatile("ldmatrix.sync.aligned.m8n8.x4.shared.b16 {%0,%1,%2,%3}, [%4];"
                 : "=r"(r[0]), "=r"(r[1]), "=r"(r[2]), "=r"(r[3]) : "r"(a));
}
__device__ __forceinline__ void mma16816(float* d, const uint32_t* a,
                                         uint32_t b0, uint32_t b1) {
    asm volatile("mma.sync.aligned.m16n8k16.row.col.f32.f16.f16.f32 "
                 "{%0,%1,%2,%3}, {%4,%5,%6,%7}, {%8,%9}, {%0,%1,%2,%3};"
                 : "+f"(d[0]), "+f"(d[1]), "+f"(d[2]), "+f"(d[3])
                 : "r"(a[0]), "r"(a[1]), "r"(a[2]), "r"(a[3]), "r"(b0), "r"(b1));
}

// ---------------- fp32 -> fp16 weight convert ----------------
__global__ void k_wcvt(const float* __restrict__ src, __half* __restrict__ dst, int n) {
    int i = (blockIdx.x * blockDim.x + threadIdx.x) * 4;
    if (i >= n) return;
    float4 v = *(const float4*)(src + i);
    ((__half2*)(dst + i))[0] = __floats2half2_rn(v.x, v.y);
    ((__half2*)(dst + i))[1] = __floats2half2_rn(v.z, v.w);
}

// ---------------- FP16 GEMM: C[M,N] = A[M,K] @ B[N,K]^T (+res)(+bias) ----------------
// single-pass fp16, fp32 accum. CTA 128x128, BK=64, 3-stage cp.async pipeline,
// ONE __syncthreads per chunk. 8 warps (2x4), warp tile 64x32.
#define HSTRIDE 144                    // bytes per smem row (128 data + 16 pad)
#define TILE_H  (128*HSTRIDE)          // 18432
#define STAGE_H (2*TILE_H)             // A + B = 36864
#define GEMM_SMEM (3*STAGE_H)          // 110592

template<int ADD_RES, int ADD_BIAS>
__global__ void __launch_bounds__(256, 2)
k_gemm_fp16(const __half* __restrict__ A, const __half* __restrict__ B,
            const float* __restrict__ Res, const float* __restrict__ bias,
            float* __restrict__ C, int Nd, int Kd)
{
    extern __shared__ char smem[];
    const uint32_t sbase = (uint32_t)__cvta_generic_to_shared(smem);

    int tid = threadIdx.x, wid = tid >> 5, lane = tid & 31;
    int bm = blockIdx.y * 128, bn = blockIdx.x * 128;
    int wm = (wid >> 2) * 64, wn = (wid & 3) * 32;

    float acc[4][4][4];
    #pragma unroll
    for (int i = 0; i < 4; i++)
        #pragma unroll
        for (int j = 0; j < 4; j++)
            #pragma unroll
            for (int q = 0; q < 4; q++) acc[i][j][q] = 0.f;

    const int nch = Kd >> 6;

    // stage loader: A and B tiles, 128 rows x 128B each -> 4 cp16/thread/tile
    auto load_stage = [&](int slot, int ch) {
        uint32_t sb = sbase + slot * STAGE_H;
        int k0 = ch << 6;
        #pragma unroll
        for (int j = 0; j < 4; j++) {
            int c = tid + j * 256;            // 0..1023
            int row = c >> 3, q = c & 7;
            uint32_t so = (uint32_t)(row * HSTRIDE + q * 16);
            size_t ga = (size_t)(bm + row) * Kd + k0 + q * 8;
            cp16(sb + so, A + ga, 16);
            int brow = bn + row;
            uint32_t sz = (brow < Nd) ? 16u : 0u;
            int brc = brow < Nd ? brow : (Nd - 1);
            size_t gb = (size_t)brc * Kd + k0 + q * 8;
            cp16(sb + TILE_H + so, B + gb, sz);
        }
        cp_commit();
    };

    load_stage(0, 0);
    if (nch > 1) load_stage(1, 1); else cp_commit();

    for (int ch = 0; ch < nch; ch++) {
        cp_wait1();
        __syncthreads();          // everyone done with stage ch-1; stage ch ready
        // prefetch into slot (ch+2)%3 == (ch-1)%3 (safe: nobody reads it anymore)
        if (ch + 2 < nch) load_stage((ch + 2) % 3, ch + 2);
        else              cp_commit();

        uint32_t sb = sbase + (ch % 3) * STAGE_H;
        uint32_t sA = sb, sB = sb + TILE_H;

        #pragma unroll
        for (int ks = 0; ks < 4; ks++) {
            // B fragments for both n16 subtiles (held across mt loop)
            uint32_t bF[2][4];
            int brow = ((lane & 16) ? 8 : 0) + (lane & 7);
            int bcb  = ks * 32 + ((lane & 8) ? 16 : 0);
            #pragma unroll
            for (int ntp = 0; ntp < 2; ntp++) {
                uint32_t bo = (uint32_t)((wn + ntp*16 + brow) * HSTRIDE + bcb);
                ldm4(bF[ntp], sB + bo);
            }
            // stream A fragments per 16-row subtile
            int arow = (lane & 15);
            int acb  = ks * 32 + ((lane & 16) ? 16 : 0);
            #pragma unroll
            for (int mt = 0; mt < 4; mt++) {
                uint32_t aF[4];
                uint32_t ao = (uint32_t)((wm + mt*16 + arow) * HSTRIDE + acb);
                ldm4(aF, sA + ao);
                #pragma unroll
                for (int ntp = 0; ntp < 2; ntp++) {
                    int nt0 = ntp * 2;
                    mma16816(acc[mt][nt0],   aF, bF[ntp][0], bF[ntp][1]);
                    mma16816(acc[mt][nt0+1], aF, bF[ntp][2], bF[ntp][3]);
                }
            }
        }
    }

    #pragma unroll
    for (int mt = 0; mt < 4; mt++) {
        int r0 = bm + wm + mt*16 + (lane >> 2);
        #pragma unroll
        for (int nt = 0; nt < 4; nt++) {
            int n = bn + wn + nt*8 + (lane & 3) * 2;
            if (n < Nd) {
                float2 v0 = make_float2(acc[mt][nt][0], acc[mt][nt][1]);
                float2 v1 = make_float2(acc[mt][nt][2], acc[mt][nt][3]);
                if (ADD_BIAS) {
                    float2 bv = *(const float2*)(bias + n);
                    v0.x += bv.x; v0.y += bv.y; v1.x += bv.x; v1.y += bv.y;
                }
                if (ADD_RES) {
                    float2 r0v = *(const float2*)(Res + (size_t)r0 * Nd + n);
                    float2 r1v = *(const float2*)(Res + (size_t)(r0+8) * Nd + n);
                    v0.x += r0v.x; v0.y += r0v.y; v1.x += r1v.x; v1.y += r1v.y;
                }
                *(float2*)(C + (size_t)r0 * Nd + n)     = v0;
                *(float2*)(C + (size_t)(r0+8) * Nd + n) = v1;
            }
        }
    }
}

// ---------------- embedding gather ----------------
__global__ void k_embed(const int* __restrict__ tok, const float* __restrict__ emb) {
    int i = blockIdx.x * blockDim.x + threadIdx.x;
    if (i < ROWS * Dd) {
        int r = i / Dd, d = i - r * Dd;
        g_x[i] = emb[(size_t)tok[r] * Dd + d];
    }
}

// ---------------- rmsnorm -> fp16 A operand ----------------
__global__ void k_rms(const float* __restrict__ rms_w) {
    __shared__ float sh[256];
    int r = blockIdx.x, t = threadIdx.x;
    float v0 = g_x[(size_t)r*Dd + t];
    float v1 = g_x[(size_t)r*Dd + t + 256];
    float ss = blockReduceSum256(v0*v0 + v1*v1, sh);
    float sc = rsqrtf(ss / (float)Dd + 1e-6f);
    g_af16[(size_t)r*Dd + t]       = __float2half_rn(v0 * sc * rms_w[t]);
    g_af16[(size_t)r*Dd + t + 256] = __float2half_rn(v1 * sc * rms_w[t + 256]);
}

// ---------------- fused conv+SiLU+head-mean+dt-softplus ----------------
__global__ __launch_bounds__(256)
void k_convdtx(const float* __restrict__ cw, const float* __restrict__ dtb) {
    int r = blockIdx.x;
    int s = r % Ss, b = r / Ss;
    int w = threadIdx.x >> 5, lane = threadIdx.x & 31;
    float sum = 0.f;
    #pragma unroll
    for (int j = 0; j < 4; j++) {
        int c = w * 128 + lane + 32 * j;
        float4 cv = ((const float4*)cw)[c];
        float acc = 0.f;
        const float* base = &g_p[(size_t)(b*Ss) * TOT + DI + c];
        if (s >= 3) {
            acc = base[(size_t)(s-3)*TOT] * cv.x + base[(size_t)(s-2)*TOT] * cv.y
                + base[(size_t)(s-1)*TOT] * cv.z + base[(size_t)s*TOT] * cv.w;
        } else {
            #pragma unroll
            for (int k = 0; k < 4; k++) {
                int sp = s + k - 3;
                if (sp >= 0) acc += base[(size_t)sp*TOT] * ((const float*)&cv)[k];
            }
        }
        sum += siluf(acc);
    }
    #pragma unroll
    for (int o = 16; o > 0; o >>= 1) sum += __shfl_xor_sync(0xffffffffu, sum, o);
    if (lane == 0) {
        g_xin[r*Hh + w] = sum * (1.f / 128.f);
        float dt = g_p[(size_t)r*TOT + 2*DI + w] + dtb[w];
        g_dt[r*Hh + w] = softplusf(dt);
    }
}

// ---------------- parallel associative scan ----------------
__global__ __launch_bounds__(256)
void k_scan(const float* __restrict__ A_log) {
    const int CH = Ss / 256;
    int chain = blockIdx.x;
    int n = chain % Nn;
    int h = (chain / Nn) % Hh;
    int b = chain / (Nn * Hh);
    float Ah = -expf(A_log[h]);

    int t = threadIdx.x;
    float hloc[CH], cA[CH];
    float a = 1.f, hv = 0.f;
    int s0 = t * CH;
    #pragma unroll
    for (int j = 0; j < CH; j++) {
        int r = b*Ss + s0 + j;
        float dt = g_dt[r*Hh + h];
        float dA = expf(dt * Ah);
        float u  = dt * g_xin[r*Hh + h] * g_p[(size_t)r*TOT + 2*DI + Hh + h*Nn + n];
        hv = dA * hv + u;
        a *= dA;
        hloc[j] = hv; cA[j] = a;
    }
    __shared__ float sA[256], sB[256];
    sA[t] = a; sB[t] = hv;
    __syncthreads();
    for (int off = 1; off < 256; off <<= 1) {
        float pa = 0.f, pb = 0.f;
        if (t >= off) { pa = sA[t - off]; pb = sB[t - off]; }
        __syncthreads();
        if (t >= off) { sB[t] = sA[t] * pb + sB[t]; sA[t] = sA[t] * pa; }
        __syncthreads();
    }
    float hin = (t == 0) ? 0.f : sB[t - 1];
    #pragma unroll
    for (int j = 0; j < CH; j++) {
        int r = b*Ss + s0 + j;
        g_hs[((size_t)r*Hh + h) * Nn + n] = hloc[j] + cA[j] * hin;
    }
}

// ---------------- y = sum_n h*C ----------------
__global__ void k_yred() {
    int i = blockIdx.x * blockDim.x + threadIdx.x;
    if (i >= ROWS * Hh) return;
    int h = i % Hh;
    int r = i / Hh;
    const float* hs = &g_hs[(size_t)i * Nn];
    const float* Cp = &g_p[(size_t)r*TOT + 2*DI + Hh + Hh*Nn + h*Nn];
    float s = 0.f;
    #pragma unroll
    for (int n = 0; n < Nn; n++) s += hs[n] * Cp[n];
    g_y[i] = s;
}

// ---------------- y_proj + gate -> fp16 A operand ----------------
__global__ void k_ymix(const float* __restrict__ yw) {
    int i = blockIdx.x * blockDim.x + threadIdx.x;
    if (i >= ROWS * DI) return;
    int c = i % DI;
    int r = i / DI;
    float4 w0 = ((const float4*)yw)[c*2];
    float4 w1 = ((const float4*)yw)[c*2 + 1];
    const float* y = &g_y[r*Hh];
    float s = y[0]*w0.x + y[1]*w0.y + y[2]*w0.z + y[3]*w0.w
            + y[4]*w1.x + y[5]*w1.y + y[6]*w1.z + y[7]*w1.w;
    float z = g_p[(size_t)r*TOT + c];
    g_af16[i] = __float2half_rn(s * siluf(z));
}

// ---------------- final layernorm -> fp16 A operand ----------------
__global__ void k_ln(const float* __restrict__ ln_w, const float* __restrict__ ln_b) {
    __shared__ float sh[256];
    int r = blockIdx.x, t = threadIdx.x;
    float v0 = g_x[(size_t)r*Dd + t];
    float v1 = g_x[(size_t)r*Dd + t + 256];
    float mu = blockReduceSum256(v0 + v1, sh) / (float)Dd;
    float d0 = v0 - mu, d1 = v1 - mu;
    float var = blockReduceSum256(d0*d0 + d1*d1, sh) / (float)Dd;
    float sc = rsqrtf(var + 1e-5f);
    g_af16[(size_t)r*Dd + t]       = __float2half_rn(d0 * sc * ln_w[t]       + ln_b[t]);
    g_af16[(size_t)r*Dd + t + 256] = __float2half_rn(d1 * sc * ln_w[t + 256] + ln_b[t + 256]);
}

// ---------------- launch ----------------
extern "C" void kernel_launch(void* const* d_in, const int* in_sizes, int n_in,
                              void* d_out, int out_size) {
    const int*   tok    = (const int*)  d_in[0];
    const float* emb    = (const float*)d_in[1];
    const float* rms_w  = (const float*)d_in[2];
    const float* in_w   = (const float*)d_in[3];
    const float* conv_w = (const float*)d_in[4];
    const float* dt_b   = (const float*)d_in[5];
    const float* A_log  = (const float*)d_in[6];
    const float* y_w    = (const float*)d_in[7];
    const float* out_w  = (const float*)d_in[8];
    const float* ln_w   = (const float*)d_in[9];
    const float* ln_b   = (const float*)d_in[10];
    const float* head_w = (const float*)d_in[11];
    const float* head_b = (const float*)d_in[12];
    float* out = (float*)d_out;

    float *p_x, *p_p;
    cudaGetSymbolAddress((void**)&p_x, g_x);
    cudaGetSymbolAddress((void**)&p_p, g_p);
    __half *p_a, *p_w;
    cudaGetSymbolAddress((void**)&p_a, g_af16);
    cudaGetSymbolAddress((void**)&p_w, g_wf16);

    static int smem_set = 0;
    if (!smem_set) {
        cudaFuncSetAttribute(k_gemm_fp16<0,0>, cudaFuncAttributeMaxDynamicSharedMemorySize, GEMM_SMEM);
        cudaFuncSetAttribute(k_gemm_fp16<1,0>, cudaFuncAttributeMaxDynamicSharedMemorySize, GEMM_SMEM);
        cudaFuncSetAttribute(k_gemm_fp16<0,1>, cudaFuncAttributeMaxDynamicSharedMemorySize, GEMM_SMEM);
        smem_set = 1;
    }

    // batched weight conversion (all layers + head) up front
    k_wcvt<<<(NLAYERS*TOT*Dd/4 + 255)/256, 256>>>(in_w,  p_w + WOFF_IN,  NLAYERS*TOT*Dd);
    k_wcvt<<<(NLAYERS*Dd*DI/4 + 255)/256, 256>>>(out_w, p_w + WOFF_OUT, NLAYERS*Dd*DI);
    k_wcvt<<<((int)((size_t)Vv*Dd/4) + 255)/256, 256>>>(head_w, p_w + WOFF_HEAD, Vv*Dd);

    k_embed<<<(ROWS*Dd + 255)/256, 256>>>(tok, emb);

    for (int L = 0; L < NLAYERS; L++) {
        k_rms<<<ROWS, 256>>>(rms_w + (size_t)L*Dd);

        // p = xn @ in_w^T  (M=4096, N=2312, K=512)
        {
            dim3 g((TOT + 127)/128, ROWS/128);
            k_gemm_fp16<0,0><<<g, 256, GEMM_SMEM>>>(p_a, p_w + WOFF_IN + (size_t)L*TOT*Dd,
                                                    nullptr, nullptr, p_p, TOT, Dd);
        }

        k_convdtx<<<ROWS, 256>>>(conv_w + (size_t)L*DI*Kk, dt_b + (size_t)L*Hh);
        k_scan<<<Bb*Hh*Nn, 256>>>(A_log + (size_t)L*Hh);
        k_yred<<<(ROWS*Hh + 255)/256, 256>>>();
        k_ymix<<<(ROWS*DI + 255)/256, 256>>>(y_w + (size_t)L*DI*Hh);

        // x = yi @ out_w^T + x  (M=4096, N=512, K=1024)
        {
            dim3 g(Dd/128, ROWS/128);
            k_gemm_fp16<1,0><<<g, 256, GEMM_SMEM>>>(p_a, p_w + WOFF_OUT + (size_t)L*Dd*DI,
                                                    p_x, nullptr, p_x, Dd, DI);
        }
    }

    k_ln<<<ROWS, 256>>>(ln_w, ln_b);

    // out = xn @ head_w^T + head_b  (M=4096, N=32000, K=512)
    {
        dim3 g(Vv/128, ROWS/128);
        k_gemm_fp16<0,1><<<g, 256, GEMM_SMEM>>>(p_a, p_w + WOFF_HEAD,
                                                nullptr, head_b, out, Vv, Dd);
    }
}